// round 14
// baseline (speedup 1.0000x reference)
#include <cuda_runtime.h>
#include <cuda_fp16.h>
#include <cstdint>

#define BB   32
#define NN   512
#define DD   256
#define HH   8
#define HDIM 32
#define EE   16384
#define ETOT (EE + NN)

// ---------------- scratch (static device globals; no allocation) -------------
__device__ float    g_xwq[BB * NN * DD];
__device__ float    g_xwk[BB * NN * DD];
__device__ float    g_xwv[BB * NN * DD];
__device__ float    g_Q  [BB * NN * DD];
__device__ float    g_K  [BB * NN * DD];
__device__ float    g_V  [BB * NN * DD];
__device__ float    g_att[BB * NN * DD];
__device__ float    g_W  [4 * DD * DD];     // tf32-rounded Wq|Wk|Wv|Wo
__device__ int      g_rowptr[NN + 1];
__device__ int2     g_edge[ETOT];           // (src, norm-as-int)
__device__ uint32_t g_bmask[NN * 16];       // packed mask bits
__device__ float    g_A[NN * NN];           // dense normalized adjacency
__device__ uint32_t g_Vh[BB * 256 * 256];   // half2-paired V: (b, kvpair, d)

// ---------------- helpers -----------------------------------------------------
__device__ __forceinline__ uint32_t f2tf32(float f) {
    uint32_t r;
    asm("cvt.rna.tf32.f32 %0, %1;" : "=r"(r) : "f"(f));
    return r;
}
__device__ __forceinline__ float4 round4(float4 v) {
    v.x = __uint_as_float(f2tf32(v.x));
    v.y = __uint_as_float(f2tf32(v.y));
    v.z = __uint_as_float(f2tf32(v.z));
    v.w = __uint_as_float(f2tf32(v.w));
    return v;
}
__device__ __forceinline__ void mma_tf32(float* c, const uint32_t* a,
                                         uint32_t b0, uint32_t b1) {
    asm volatile(
        "mma.sync.aligned.m16n8k8.row.col.f32.tf32.tf32.f32 "
        "{%0,%1,%2,%3}, {%4,%5,%6,%7}, {%8,%9}, {%0,%1,%2,%3};"
        : "+f"(c[0]), "+f"(c[1]), "+f"(c[2]), "+f"(c[3])
        : "r"(a[0]), "r"(a[1]), "r"(a[2]), "r"(a[3]), "r"(b0), "r"(b1));
}
__device__ __forceinline__ void mma_f16(float* c, const uint32_t* a,
                                        uint32_t b0, uint32_t b1) {
    asm volatile(
        "mma.sync.aligned.m16n8k16.row.col.f32.f16.f16.f32 "
        "{%0,%1,%2,%3}, {%4,%5,%6,%7}, {%8,%9}, {%0,%1,%2,%3};"
        : "+f"(c[0]), "+f"(c[1]), "+f"(c[2]), "+f"(c[3])
        : "r"(a[0]), "r"(a[1]), "r"(a[2]), "r"(a[3]), "r"(b0), "r"(b1));
}
__device__ __forceinline__ uint32_t h2bits(float a, float b) {
    __half2 h = __floats2half2_rn(a, b);
    return *reinterpret_cast<uint32_t*>(&h);
}
__device__ __forceinline__ void cp16(uint32_t saddr, const void* g) {
    asm volatile("cp.async.ca.shared.global [%0], [%1], 16;"
                 :: "r"(saddr), "l"(g) : "memory");
}
#define CP_COMMIT() asm volatile("cp.async.commit_group;" ::: "memory")
#define CP_WAIT0()  asm volatile("cp.async.wait_group 0;" ::: "memory")

// ---------------- prep: round inputs+W to tf32, zero A, pack mask -------------
__global__ void k_round(const float* __restrict__ q, const float* __restrict__ k,
                        const float* __restrict__ v,
                        const float* __restrict__ wq, const float* __restrict__ wk,
                        const float* __restrict__ wv, const float* __restrict__ wo,
                        const int* __restrict__ mask) {
    int idx = blockIdx.x * 256 + threadIdx.x;      // 0..524287
    #pragma unroll
    for (int t = 0; t < 6; t++) {
        int i = idx + t * 524288;                  // 0..3145727
        int j   = i >> 20;                         // tensor select
        int off = i & 0xFFFFF;
        const float4* s = (j == 0) ? (const float4*)q
                        : (j == 1) ? (const float4*)k : (const float4*)v;
        float4* d = (j == 0) ? (float4*)g_Q
                  : (j == 1) ? (float4*)g_K : (float4*)g_V;
        d[off] = round4(s[off]);
    }
    if (idx < 65536) {
        int j = idx >> 14;                         // W select
        int off = idx & 16383;
        const float4* ws = (j == 0) ? (const float4*)wq
                         : (j == 1) ? (const float4*)wk
                         : (j == 2) ? (const float4*)wv : (const float4*)wo;
        ((float4*)g_W)[idx] = round4(ws[off]);
        ((float4*)g_A)[idx] = make_float4(0.f, 0.f, 0.f, 0.f);
    }
    if (idx < NN * 16) {
        int r  = idx >> 4;
        int wd = idx & 15;
        const int* mrow = mask + (size_t)r * NN + wd * 32;
        uint32_t bits = 0;
        #pragma unroll
        for (int jb = 0; jb < 32; jb++) bits |= (mrow[jb] ? 1u : 0u) << jb;
        g_bmask[idx] = bits;
    }
}

// ---------------- fused single-CTA graph prep + dense A fill ------------------
__global__ __launch_bounds__(NN) void k_graph(const int* __restrict__ edge) {
    __shared__ int sdeg[NN];
    __shared__ int scnt[NN];
    __shared__ int srow[NN];
    __shared__ int ss[NN];
    __shared__ int se64;
    int t = threadIdx.x;

    if (t == 0) {
        int nz = 0;
        for (int i = 0; i < 64; i++) nz += (edge[2 * i + 1] != 0);
        se64 = (nz == 0) ? 1 : 0;
    }
    sdeg[t] = 0;
    scnt[t] = 0;
    __syncthreads();
    int e64 = se64;

    for (int e = t; e < ETOT; e += NN) {
        int dst = (e < EE) ? (e64 ? edge[2 * (EE + e)] : edge[EE + e]) : (e - EE);
        if (dst >= 0 && dst < NN) atomicAdd(&sdeg[dst], 1);
    }
    __syncthreads();

    ss[t] = sdeg[t];
    __syncthreads();
    for (int off = 1; off < NN; off <<= 1) {
        int v = (t >= off) ? ss[t - off] : 0;
        __syncthreads();
        ss[t] += v;
        __syncthreads();
    }
    srow[t] = ss[t] - sdeg[t];
    g_rowptr[t + 1] = ss[t];
    if (t == 0) g_rowptr[0] = 0;
    __syncthreads();

    for (int e = t; e < ETOT; e += NN) {
        int s, d;
        if (e < EE) {
            s = e64 ? edge[2 * e] : edge[e];
            d = e64 ? edge[2 * (EE + e)] : edge[EE + e];
        } else {
            s = e - EE; d = e - EE;
        }
        if (s < 0 || s >= NN || d < 0 || d >= NN) continue;
        float nm = rsqrtf((float)sdeg[s]) * rsqrtf((float)sdeg[d]);
        int pos = srow[d] + atomicAdd(&scnt[d], 1);
        g_edge[pos] = make_int2(s, __float_as_int(nm));
    }
    __syncthreads();

    // per-row serial edge fill into pre-zeroed A (deterministic)
    float* arow = g_A + (size_t)t * NN;
    for (int i = srow[t]; i < ss[t]; i++) {
        int2 e = g_edge[i];
        arow[e.x] += __int_as_float(e.y);
    }
}

// ---------------- cp.async GEMM (pre-rounded operands), K=256 -----------------
#define AS_STRIDE 36
#define BS_STRIDE 132
#define GA_ABUF (128 * AS_STRIDE)
#define GA_BBUF (32 * BS_STRIDE)
#define GA_SMEM ((2 * GA_ABUF + 2 * GA_BBUF + 128) * 4)

__global__ __launch_bounds__(256) void k_gemm_ca(
    const float* __restrict__ a0p, const float* __restrict__ a1p,
    const float* __restrict__ a2p,
    const float* __restrict__ Wall,
    float* __restrict__ c0p, float* __restrict__ c1p, float* __restrict__ c2p,
    const float* __restrict__ bias, int roundC)
{
    const int z = blockIdx.z;
    int tid = threadIdx.x;

    if (z == 3) {
        // service CTAs: round dense A to tf32 (post-k_graph, coalesced)
        int cta = blockIdx.x * 128 + blockIdx.y;    // 0..255
        int i4  = cta * 256 + tid;
        ((float4*)g_A)[i4] = round4(((float4*)g_A)[i4]);
        return;
    }

    extern __shared__ uint32_t dsm[];
    uint32_t* Asb = dsm;
    uint32_t* Bsb = dsm + 2 * GA_ABUF;
    float*    bsh = (float*)(dsm + 2 * GA_ABUF + 2 * GA_BBUF);

    const float* A  = (z == 0) ? a0p : (z == 1) ? a1p : a2p;
    const float* Wp = Wall + (size_t)z * DD * DD;
    float*       C  = (z == 0) ? c0p : (z == 1) ? c1p : c2p;

    const int n0 = blockIdx.x * 128;
    const int m0 = blockIdx.y * 128;

    int wid  = tid >> 5;
    int lane = tid & 31;
    int grp  = lane >> 2;
    int tig  = lane & 3;
    int wm   = (wid & 1) * 64;
    int wn   = (wid >> 1) * 32;

    if (tid < 128) bsh[tid] = bias ? bias[n0 + tid] : 0.f;

    uint32_t sA = (uint32_t)__cvta_generic_to_shared(Asb);
    uint32_t sB = (uint32_t)__cvta_generic_to_shared(Bsb);

    float acc[4][4][4];
    #pragma unroll
    for (int i = 0; i < 4; i++)
        #pragma unroll
        for (int j = 0; j < 4; j++)
            #pragma unroll
            for (int r = 0; r < 4; r++) acc[i][j][r] = 0.f;

    #pragma unroll
    for (int t = 0; t < 4; t++) {
        int i = tid + t * 256;
        int row = i >> 3, q = (i & 7) * 4;
        cp16(sA + (row * AS_STRIDE + q) * 4, A + (size_t)(m0 + row) * 256 + q);
    }
    #pragma unroll
    for (int t = 0; t < 4; t++) {
        int i = tid + t * 256;
        int k = i >> 5, q = (i & 31) * 4;
        cp16(sB + (k * BS_STRIDE + q) * 4, Wp + (size_t)k * 256 + n0 + q);
    }
    CP_COMMIT();

    for (int c = 0; c < 8; c++) {
        CP_WAIT0();
        __syncthreads();

        if (c + 1 < 8) {
            int k0  = (c + 1) * 32;
            int buf = (c + 1) & 1;
            uint32_t dA = sA + buf * GA_ABUF * 4;
            uint32_t dB = sB + buf * GA_BBUF * 4;
            #pragma unroll
            for (int t = 0; t < 4; t++) {
                int i = tid + t * 256;
                int row = i >> 3, q = (i & 7) * 4;
                cp16(dA + (row * AS_STRIDE + q) * 4,
                     A + (size_t)(m0 + row) * 256 + k0 + q);
            }
            #pragma unroll
            for (int t = 0; t < 4; t++) {
                int i = tid + t * 256;
                int k = i >> 5, q = (i & 31) * 4;
                cp16(dB + (k * BS_STRIDE + q) * 4,
                     Wp + (size_t)(k0 + k) * 256 + n0 + q);
            }
            CP_COMMIT();
        }

        const uint32_t* As = Asb + (c & 1) * GA_ABUF;
        const uint32_t* Bs = Bsb + (c & 1) * GA_BBUF;

        #pragma unroll
        for (int ks = 0; ks < 4; ks++) {
            int kk = ks * 8;
            uint32_t af[4][4], bf[4][2];
            #pragma unroll
            for (int mt = 0; mt < 4; mt++) {
                int r = wm + mt * 16 + grp;
                af[mt][0] = As[r * AS_STRIDE + kk + tig];
                af[mt][1] = As[(r + 8) * AS_STRIDE + kk + tig];
                af[mt][2] = As[r * AS_STRIDE + kk + tig + 4];
                af[mt][3] = As[(r + 8) * AS_STRIDE + kk + tig + 4];
            }
            #pragma unroll
            for (int nt = 0; nt < 4; nt++) {
                int cc = wn + nt * 8 + grp;
                bf[nt][0] = Bs[(kk + tig) * BS_STRIDE + cc];
                bf[nt][1] = Bs[(kk + tig + 4) * BS_STRIDE + cc];
            }
            #pragma unroll
            for (int mt = 0; mt < 4; mt++)
                #pragma unroll
                for (int nt = 0; nt < 4; nt++)
                    mma_tf32(acc[mt][nt], af[mt], bf[nt][0], bf[nt][1]);
        }
        __syncthreads();
    }

    #pragma unroll
    for (int mt = 0; mt < 4; mt++) {
        #pragma unroll
        for (int nt = 0; nt < 4; nt++) {
            int cc = wn + nt * 8 + tig * 2;
            float b0 = bsh[cc], b1 = bsh[cc + 1];
            size_t r0 = (size_t)(m0 + wm + mt * 16 + grp) * 256 + n0 + cc;
            size_t r1 = r0 + 8 * 256;
            float2 v0 = {acc[mt][nt][0] + b0, acc[mt][nt][1] + b1};
            float2 v1 = {acc[mt][nt][2] + b0, acc[mt][nt][3] + b1};
            if (roundC) {
                v0.x = __uint_as_float(f2tf32(v0.x));
                v0.y = __uint_as_float(f2tf32(v0.y));
                v1.x = __uint_as_float(f2tf32(v1.x));
                v1.y = __uint_as_float(f2tf32(v1.y));
            }
            *(float2*)(C + r0) = v0;
            *(float2*)(C + r1) = v1;
        }
    }
}

// ---------------- aggregation GEMM, cp.async 2-stage; outputs tf32-rounded ----
#define AGG_ABUF (128 * AS_STRIDE)
#define AGG_BBUF (32 * BS_STRIDE)
#define AGG_SMEM ((2 * AGG_ABUF + 2 * AGG_BBUF + 128) * 4)

__global__ __launch_bounds__(256) void k_agg_gemm(
    const float* __restrict__ xq, const float* __restrict__ xk,
    const float* __restrict__ xv,
    const float* __restrict__ bq, const float* __restrict__ bk,
    const float* __restrict__ bv,
    float* __restrict__ oq, float* __restrict__ ok_, float* __restrict__ ov)
{
    extern __shared__ uint32_t dsm[];
    uint32_t* Asb = dsm;
    uint32_t* Bsb = dsm + 2 * AGG_ABUF;
    float*    bsh = (float*)(dsm + 2 * AGG_ABUF + 2 * AGG_BBUF);

    int zz = blockIdx.z;
    int z  = zz >> 5;
    int b  = zz & 31;
    const float* X    = (z == 0) ? xq : (z == 1) ? xk : xv;
    const float* bias = (z == 0) ? bq : (z == 1) ? bk : bv;
    float*       O    = (z == 0) ? oq : (z == 1) ? ok_ : ov;
    const float* Xb = X + (size_t)b * NN * DD;
    float*       Cb = O + (size_t)b * NN * DD;

    const int n0 = blockIdx.x * 128;
    const int m0 = blockIdx.y * 128;

    int tid  = threadIdx.x;
    int wid  = tid >> 5;
    int lane = tid & 31;
    int grp  = lane >> 2;
    int tig  = lane & 3;
    int wm   = (wid & 1) * 64;
    int wn   = (wid >> 1) * 32;

    if (tid < 128) bsh[tid] = bias[n0 + tid];

    uint32_t sA = (uint32_t)__cvta_generic_to_shared(Asb);
    uint32_t sB = (uint32_t)__cvta_generic_to_shared(Bsb);

    float acc[4][4][4];
    #pragma unroll
    for (int i = 0; i < 4; i++)
        #pragma unroll
        for (int j = 0; j < 4; j++)
            #pragma unroll
            for (int r = 0; r < 4; r++) acc[i][j][r] = 0.f;

    #pragma unroll
    for (int t = 0; t < 4; t++) {
        int i = tid + t * 256;
        int row = i >> 3, q = (i & 7) * 4;
        cp16(sA + (row * AS_STRIDE + q) * 4, g_A + (size_t)(m0 + row) * NN + q);
    }
    #pragma unroll
    for (int t = 0; t < 4; t++) {
        int i = tid + t * 256;
        int k = i >> 5, q = (i & 31) * 4;
        cp16(sB + (k * BS_STRIDE + q) * 4, Xb + (size_t)k * 256 + n0 + q);
    }
    CP_COMMIT();

    for (int c = 0; c < 16; c++) {
        CP_WAIT0();
        __syncthreads();

        if (c + 1 < 16) {
            int k0  = (c + 1) * 32;
            int buf = (c + 1) & 1;
            uint32_t dA = sA + buf * AGG_ABUF * 4;
            uint32_t dB = sB + buf * AGG_BBUF * 4;
            #pragma unroll
            for (int t = 0; t < 4; t++) {
                int i = tid + t * 256;
                int row = i >> 3, q = (i & 7) * 4;
                cp16(dA + (row * AS_STRIDE + q) * 4,
                     g_A + (size_t)(m0 + row) * NN + k0 + q);
            }
            #pragma unroll
            for (int t = 0; t < 4; t++) {
                int i = tid + t * 256;
                int k = i >> 5, q = (i & 31) * 4;
                cp16(dB + (k * BS_STRIDE + q) * 4,
                     Xb + (size_t)(k0 + k) * 256 + n0 + q);
            }
            CP_COMMIT();
        }

        const uint32_t* As = Asb + (c & 1) * AGG_ABUF;
        const uint32_t* Bs = Bsb + (c & 1) * AGG_BBUF;

        #pragma unroll
        for (int ks = 0; ks < 4; ks++) {
            int kk = ks * 8;
            uint32_t af[4][4], bf[4][2];
            #pragma unroll
            for (int mt = 0; mt < 4; mt++) {
                int r = wm + mt * 16 + grp;
                af[mt][0] = As[r * AS_STRIDE + kk + tig];
                af[mt][1] = As[(r + 8) * AS_STRIDE + kk + tig];
                af[mt][2] = As[r * AS_STRIDE + kk + tig + 4];
                af[mt][3] = As[(r + 8) * AS_STRIDE + kk + tig + 4];
            }
            #pragma unroll
            for (int nt = 0; nt < 4; nt++) {
                int cc = wn + nt * 8 + grp;
                bf[nt][0] = Bs[(kk + tig) * BS_STRIDE + cc];
                bf[nt][1] = Bs[(kk + tig + 4) * BS_STRIDE + cc];
            }
            #pragma unroll
            for (int mt = 0; mt < 4; mt++)
                #pragma unroll
                for (int nt = 0; nt < 4; nt++)
                    mma_tf32(acc[mt][nt], af[mt], bf[nt][0], bf[nt][1]);
        }
        __syncthreads();
    }

    #pragma unroll
    for (int mt = 0; mt < 4; mt++) {
        #pragma unroll
        for (int nt = 0; nt < 4; nt++) {
            int cc = wn + nt * 8 + tig * 2;
            float b0 = bsh[cc], b1 = bsh[cc + 1];
            size_t r0 = (size_t)(m0 + wm + mt * 16 + grp) * 256 + n0 + cc;
            size_t r1 = r0 + 8 * 256;
            float2 v0, v1;
            v0.x = __uint_as_float(f2tf32(acc[mt][nt][0] + b0));
            v0.y = __uint_as_float(f2tf32(acc[mt][nt][1] + b1));
            v1.x = __uint_as_float(f2tf32(acc[mt][nt][2] + b0));
            v1.y = __uint_as_float(f2tf32(acc[mt][nt][3] + b1));
            *(float2*)(Cb + r0) = v0;
            *(float2*)(Cb + r1) = v1;
        }
    }
}

// ---------------- V -> half2-paired copy (g_V -> g_Vh) ------------------------
__global__ void k_vh() {
    int idx = blockIdx.x * 256 + threadIdx.x;     // 524288
    int dq = (idx & 63) * 4;
    int p  = (idx >> 6) & 255;
    int b  = idx >> 14;
    const float* v0 = g_V + ((size_t)b * NN + 2 * p) * DD + dq;
    float4 x0 = *(const float4*)v0;
    float4 x1 = *(const float4*)(v0 + DD);
    uint4 o;
    o.x = h2bits(x0.x, x1.x);
    o.y = h2bits(x0.y, x1.y);
    o.z = h2bits(x0.z, x1.z);
    o.w = h2bits(x0.w, x1.w);
    *(uint4*)(g_Vh + ((size_t)(b * 256 + p) * 256 + dq)) = o;
}

// ---------------- flash attention: tf32 QK + fp16 PV (shuffle-free) -----------
#define KW      36
#define KWORDS  (64 * KW)
#define VWORDS  (32 * KW)
#define BUFW    (KWORDS + VWORDS)
#define ATT_SMEM (2 * BUFW * 4)

__global__ __launch_bounds__(256, 2) void k_attn(
    const float* __restrict__ Q, const float* __restrict__ K,
    float* __restrict__ out)
{
    extern __shared__ uint32_t sm[];

    int h   = blockIdx.y;
    int b   = blockIdx.z;
    int tid = threadIdx.x;
    int wid = tid >> 5, lane = tid & 31;
    int grp = lane >> 2, tig = lane & 3;
    int qw  = blockIdx.x * 128 + wid * 16;

    const float* Qb = Q + (size_t)b * NN * DD + h * HDIM;
    const float* Kb = K + (size_t)b * NN * DD + h * HDIM;

    const float escale = 0.17677669529663687f;

    uint32_t qa[4][4];
    #pragma unroll
    for (int kf = 0; kf < 4; kf++) {
        int cl = kf * 8 + tig;
        qa[kf][0] = __float_as_uint(Qb[(size_t)(qw + grp) * DD + cl]);
        qa[kf][1] = __float_as_uint(Qb[(size_t)(qw + grp + 8) * DD + cl]);
        qa[kf][2] = __float_as_uint(Qb[(size_t)(qw + grp) * DD + cl + 4]);
        qa[kf][3] = __float_as_uint(Qb[(size_t)(qw + grp + 8) * DD + cl + 4]);
    }

    float m0 = -3.4e38f, m1 = -3.4e38f, l0 = 0.f, l1 = 0.f;
    float oacc[4][4];
    #pragma unroll
    for (int nt = 0; nt < 4; nt++)
        #pragma unroll
        for (int r = 0; r < 4; r++) oacc[nt][r] = 0.f;

    const uint32_t* bm0 = g_bmask + (size_t)(qw + grp) * 16;
    const uint32_t* bm1 = g_bmask + (size_t)(qw + grp + 8) * 16;

    uint32_t sbase = (uint32_t)__cvta_generic_to_shared(sm);
    int vp = tid >> 3, vq = (tid & 7) * 4;

    #pragma unroll
    for (int t = 0; t < 2; t++) {
        int i = tid + t * 256;
        int r = i >> 3, f = (i & 7) * 4;
        cp16(sbase + (r * KW + f) * 4, Kb + (size_t)r * DD + f);
    }
    cp16(sbase + (KWORDS + vp * KW + vq) * 4,
         g_Vh + (size_t)(b * 256 + vp) * 256 + h * HDIM + vq);
    CP_COMMIT();

    for (int ci = 0; ci < 8; ci++) {
        CP_WAIT0();
        __syncthreads();

        if (ci + 1 < 8) {
            int c1  = (ci + 1) * 64;
            uint32_t dst = sbase + ((ci + 1) & 1) * BUFW * 4;
            #pragma unroll
            for (int t = 0; t < 2; t++) {
                int i = tid + t * 256;
                int r = i >> 3, f = (i & 7) * 4;
                cp16(dst + (r * KW + f) * 4, Kb + (size_t)(c1 + r) * DD + f);
            }
            cp16(dst + (KWORDS + vp * KW + vq) * 4,
                 g_Vh + (size_t)(b * 256 + (ci + 1) * 32 + vp) * 256 + h * HDIM + vq);
            CP_COMMIT();
        }

        const uint32_t* Ks = sm + (ci & 1) * BUFW;
        const uint32_t* Vs = Ks + KWORDS;
        int c0 = ci * 64;

        float sacc[8][4];
        #pragma unroll
        for (int nt = 0; nt < 8; nt++)
            #pragma unroll
            for (int r = 0; r < 4; r++) sacc[nt][r] = 0.f;
        #pragma unroll
        for (int nt = 0; nt < 8; nt++)
            #pragma unroll
            for (int kf = 0; kf < 4; kf++) {
                uint32_t b0v = Ks[(nt * 8 + grp) * KW + kf * 8 + tig];
                uint32_t b1v = Ks[(nt * 8 + grp) * KW + kf * 8 + tig + 4];
                mma_tf32(sacc[nt], qa[kf], b0v, b1v);
            }

        uint32_t wa0 = bm0[c0 >> 5], wa1 = bm0[(c0 >> 5) + 1];
        uint32_t wb0 = bm1[c0 >> 5], wb1 = bm1[(c0 >> 5) + 1];
        float cm0 = -3.4e38f, cm1 = -3.4e38f;
        #pragma unroll
        for (int nt = 0; nt < 8; nt++) {
            int j  = nt * 8 + 2 * tig;
            uint32_t wa = (j < 32) ? wa0 : wa1;
            uint32_t wb = (j < 32) ? wb0 : wb1;
            int sh = j & 31;
            if (!((wa >> sh) & 1))        sacc[nt][0] = -1e10f;
            if (!((wa >> (sh + 1)) & 1))  sacc[nt][1] = -1e10f;
            if (!((wb >> sh) & 1))        sacc[nt][2] = -1e10f;
            if (!((wb >> (sh + 1)) & 1))  sacc[nt][3] = -1e10f;
            cm0 = fmaxf(cm0, fmaxf(sacc[nt][0], sacc[nt][1]));
            cm1 = fmaxf(cm1, fmaxf(sacc[nt][2], sacc[nt][3]));
        }
        cm0 = fmaxf(cm0, __shfl_xor_sync(0xffffffffu, cm0, 1));
        cm0 = fmaxf(cm0, __shfl_xor_sync(0xffffffffu, cm0, 2));
        cm1 = fmaxf(cm1, __shfl_xor_sync(0xffffffffu, cm1, 1));
        cm1 = fmaxf(cm1, __shfl_xor_sync(0xffffffffu, cm1, 2));

        float nm0 = fmaxf(m0, cm0), nm1 = fmaxf(m1, cm1);
        float f0 = __expf((m0 - nm0) * escale), f1 = __expf((m1 - nm1) * escale);
        l0 *= f0; l1 *= f1;
        #pragma unroll
        for (int nt = 0; nt < 4; nt++) {
            oacc[nt][0] *= f0; oacc[nt][1] *= f0;
            oacc[nt][2] *= f1; oacc[nt][3] *= f1;
        }
        m0 = nm0; m1 = nm1;

        uint32_t h2a[8], h2b[8];
        #pragma unroll
        for (int nt = 0; nt < 8; nt++) {
            float p0 = __expf((sacc[nt][0] - nm0) * escale);
            float p1 = __expf((sacc[nt][1] - nm0) * escale);
            float p2 = __expf((sacc[nt][2] - nm1) * escale);
            float p3 = __expf((sacc[nt][3] - nm1) * escale);
            l0 += p0 + p1; l1 += p2 + p3;
            h2a[nt] = h2bits(p0, p1);
            h2b[nt] = h2bits(p2, p3);
        }

        #pragma unroll
        for (int s = 0; s < 4; s++) {
            uint32_t pa[4];
            pa[0] = h2a[2 * s];
            pa[1] = h2b[2 * s];
            pa[2] = h2a[2 * s + 1];
            pa[3] = h2b[2 * s + 1];
            #pragma unroll
            for (int nt = 0; nt < 4; nt++) {
                uint32_t b0v = Vs[(s * 8 + tig) * KW + nt * 8 + grp];
                uint32_t b1v = Vs[(s * 8 + tig + 4) * KW + nt * 8 + grp];
                mma_f16(oacc[nt], pa, b0v, b1v);
            }
        }
    }

    l0 += __shfl_xor_sync(0xffffffffu, l0, 1);
    l0 += __shfl_xor_sync(0xffffffffu, l0, 2);
    l1 += __shfl_xor_sync(0xffffffffu, l1, 1);
    l1 += __shfl_xor_sync(0xffffffffu, l1, 2);
    float inv0 = 1.f / l0, inv1 = 1.f / l1;

    // epilogue: normalize + tf32-round (outproj raw-copies these bits)
    float* o0 = out + ((size_t)b * NN + qw + grp) * DD + h * HDIM;
    float* o1 = out + ((size_t)b * NN + qw + grp + 8) * DD + h * HDIM;
    #pragma unroll
    for (int nt = 0; nt < 4; nt++) {
        int cl = nt * 8 + 2 * tig;
        float2 v0, v1;
        v0.x = __uint_as_float(f2tf32(oacc[nt][0] * inv0));
        v0.y = __uint_as_float(f2tf32(oacc[nt][1] * inv0));
        v1.x = __uint_as_float(f2tf32(oacc[nt][2] * inv1));
        v1.y = __uint_as_float(f2tf32(oacc[nt][3] * inv1));
        *(float2*)(o0 + cl) = v0;
        *(float2*)(o1 + cl) = v1;
    }
}

// ---------------- launch ------------------------------------------------------
extern "C" void kernel_launch(void* const* d_in, const int* in_sizes, int n_in,
                              void* d_out, int out_size) {
    const float* query = (const float*)d_in[0];
    const float* key   = (const float*)d_in[1];
    const float* value = (const float*)d_in[2];
    const int*   edge  = (const int*)d_in[3];
    const int*   mask  = (const int*)d_in[4];
    const float* Wq = (const float*)d_in[5];
    const float* bq = (const float*)d_in[6];
    const float* Wk = (const float*)d_in[7];
    const float* bk = (const float*)d_in[8];
    const float* Wv = (const float*)d_in[9];
    const float* bv = (const float*)d_in[10];
    const float* Wo = (const float*)d_in[11];
    const float* bo = (const float*)d_in[12];
    float* out = (float*)d_out;

    float *xwq, *xwk, *xwv, *Qp, *Kp, *Vp, *att, *Wg;
    cudaGetSymbolAddress((void**)&xwq, g_xwq);
    cudaGetSymbolAddress((void**)&xwk, g_xwk);
    cudaGetSymbolAddress((void**)&xwv, g_xwv);
    cudaGetSymbolAddress((void**)&Qp,  g_Q);
    cudaGetSymbolAddress((void**)&Kp,  g_K);
    cudaGetSymbolAddress((void**)&Vp,  g_V);
    cudaGetSymbolAddress((void**)&att, g_att);
    cudaGetSymbolAddress((void**)&Wg,  g_W);

    cudaFuncSetAttribute(k_attn, cudaFuncAttributeMaxDynamicSharedMemorySize,
                         ATT_SMEM);
    cudaFuncSetAttribute(k_agg_gemm, cudaFuncAttributeMaxDynamicSharedMemorySize,
                         AGG_SMEM);
    cudaFuncSetAttribute(k_gemm_ca, cudaFuncAttributeMaxDynamicSharedMemorySize,
                         GA_SMEM);

    // 1: round inputs+weights to tf32, zero A, pack mask
    k_round<<<2048, 256>>>(query, key, value, Wq, Wk, Wv, Wo, mask);

    // 2: graph prep + dense adjacency fill (single CTA)
    k_graph<<<1, NN>>>(edge);

    // 3: fused QKV projection, cp.async raw (+z=3 service: round A)
    k_gemm_ca<<<dim3(2, 128, 4), 256, GA_SMEM>>>(Qp, Kp, Vp, Wg,
                                                 xwq, xwk, xwv, nullptr, 1);

    // 4: aggregation GEMM (+bias, tf32-rounded outputs)  (<- ncu capture slot)
    k_agg_gemm<<<dim3(2, 4, 96), 256, AGG_SMEM>>>(xwq, xwk, xwv,
                                                  bq, bk, bv, Qp, Kp, Vp);

    // 5: pair V into half2 (g_V -> g_Vh)
    k_vh<<<2048, 256>>>();

    // 6: flash attention (tf32 QK + fp16 PV); outputs tf32-rounded
    k_attn<<<dim3(4, HH, BB), 256, ATT_SMEM>>>(Qp, Kp, att);

    // 7: output projection, cp.async raw (+bias, fp32 epilogue) into d_out
    k_gemm_ca<<<dim3(2, 128, 1), 256, GA_SMEM>>>(att, att, att,
                                                 Wg + 3 * DD * DD,
                                                 out, out, out, bo, 0);
}

// round 15
// speedup vs baseline: 1.2254x; 1.2254x over previous
#include <cuda_runtime.h>
#include <cuda_fp16.h>
#include <cstdint>

#define BB   32
#define NN   512
#define DD   256
#define HH   8
#define HDIM 32
#define EE   16384
#define ETOT (EE + NN)

// ---------------- scratch (static device globals; no allocation) -------------
__device__ float    g_xwq[BB * NN * DD];
__device__ float    g_xwk[BB * NN * DD];
__device__ float    g_xwv[BB * NN * DD];
__device__ float    g_Q  [BB * NN * DD];
__device__ float    g_K  [BB * NN * DD];
__device__ float    g_V  [BB * NN * DD];
__device__ int      g_rowptr[NN + 1];
__device__ int2     g_edge[ETOT];
__device__ uint32_t g_bmask[NN * 16];
__device__ float    g_A[NN * NN];                 // fp32 adjacency (built once)
__device__ uint32_t g_Ah[NN * 256];               // fp16 adjacency, row-major pairs
__device__ uint32_t g_Xh[3 * BB * NN * 128];      // fp16 q/k/v inputs row-major
__device__ uint32_t g_Wp[4 * 128 * 256];          // fp16 W k-pair-packed [pair][n]
__device__ uint32_t g_xwP[3 * BB * 256 * 256];    // fp16 xw k-pair-packed
__device__ uint32_t g_Vh[BB * 256 * 256];         // fp16 V pairs (attention PV)
__device__ uint32_t g_atth[BB * NN * 128];        // fp16 attention output

// ---------------- helpers -----------------------------------------------------
__device__ __forceinline__ uint32_t f2tf32(float f) {
    uint32_t r;
    asm("cvt.rna.tf32.f32 %0, %1;" : "=r"(r) : "f"(f));
    return r;
}
__device__ __forceinline__ void mma_tf32(float* c, const uint32_t* a,
                                         uint32_t b0, uint32_t b1) {
    asm volatile(
        "mma.sync.aligned.m16n8k8.row.col.f32.tf32.tf32.f32 "
        "{%0,%1,%2,%3}, {%4,%5,%6,%7}, {%8,%9}, {%0,%1,%2,%3};"
        : "+f"(c[0]), "+f"(c[1]), "+f"(c[2]), "+f"(c[3])
        : "r"(a[0]), "r"(a[1]), "r"(a[2]), "r"(a[3]), "r"(b0), "r"(b1));
}
__device__ __forceinline__ void mma_f16(float* c, const uint32_t* a,
                                        uint32_t b0, uint32_t b1) {
    asm volatile(
        "mma.sync.aligned.m16n8k16.row.col.f32.f16.f16.f32 "
        "{%0,%1,%2,%3}, {%4,%5,%6,%7}, {%8,%9}, {%0,%1,%2,%3};"
        : "+f"(c[0]), "+f"(c[1]), "+f"(c[2]), "+f"(c[3])
        : "r"(a[0]), "r"(a[1]), "r"(a[2]), "r"(a[3]), "r"(b0), "r"(b1));
}
__device__ __forceinline__ uint32_t h2bits(float a, float b) {
    __half2 h = __floats2half2_rn(a, b);
    return *reinterpret_cast<uint32_t*>(&h);
}
__device__ __forceinline__ void cp16(uint32_t saddr, const void* g) {
    asm volatile("cp.async.ca.shared.global [%0], [%1], 16;"
                 :: "r"(saddr), "l"(g) : "memory");
}
#define CP_COMMIT() asm volatile("cp.async.commit_group;" ::: "memory")
#define CP_WAIT0()  asm volatile("cp.async.wait_group 0;" ::: "memory")

// ---------------- prep: inputs->fp16, W->fp16 pairs, zero A, pack mask --------
__global__ void k_round(const float* __restrict__ q, const float* __restrict__ k,
                        const float* __restrict__ v,
                        const float* __restrict__ wq, const float* __restrict__ wk,
                        const float* __restrict__ wv, const float* __restrict__ wo,
                        const int* __restrict__ mask) {
    int idx = blockIdx.x * 256 + threadIdx.x;      // 0..524287
    #pragma unroll
    for (int t = 0; t < 6; t++) {
        int i = idx + t * 524288;                  // 3*1048576 float4s
        int j   = i >> 20;
        int off = i & 0xFFFFF;
        const float4* s = (j == 0) ? (const float4*)q
                        : (j == 1) ? (const float4*)k : (const float4*)v;
        float4 x = s[off];
        uint2 o;
        o.x = h2bits(x.x, x.y);
        o.y = h2bits(x.z, x.w);
        *(uint2*)(g_Xh + (size_t)j * 2097152 + (size_t)off * 2) = o;
    }
    if (idx < 65536) {
        // W -> k-pair-packed fp16
        int j   = idx >> 14;
        int rem = idx & 16383;
        int p   = rem >> 7;
        int n2  = (rem & 127) * 2;
        const float* w = (j == 0) ? wq : (j == 1) ? wk : (j == 2) ? wv : wo;
        float2 e = *(const float2*)(w + (size_t)(2 * p) * 256 + n2);
        float2 o = *(const float2*)(w + (size_t)(2 * p + 1) * 256 + n2);
        uint2 u;
        u.x = h2bits(e.x, o.x);
        u.y = h2bits(e.y, o.y);
        *(uint2*)(g_Wp + (size_t)(j * 128 + p) * 256 + n2) = u;
        // zero dense A
        ((float4*)g_A)[idx] = make_float4(0.f, 0.f, 0.f, 0.f);
    }
    if (idx < NN * 16) {
        int r  = idx >> 4;
        int wd = idx & 15;
        const int* mrow = mask + (size_t)r * NN + wd * 32;
        uint32_t bits = 0;
        #pragma unroll
        for (int jb = 0; jb < 32; jb++) bits |= (mrow[jb] ? 1u : 0u) << jb;
        g_bmask[idx] = bits;
    }
}

// ---------------- fused single-CTA graph prep + dense A fill ------------------
__global__ __launch_bounds__(NN) void k_graph(const int* __restrict__ edge) {
    __shared__ int sdeg[NN];
    __shared__ int scnt[NN];
    __shared__ int srow[NN];
    __shared__ int ss[NN];
    __shared__ int se64;
    int t = threadIdx.x;

    if (t == 0) {
        int nz = 0;
        for (int i = 0; i < 64; i++) nz += (edge[2 * i + 1] != 0);
        se64 = (nz == 0) ? 1 : 0;
    }
    sdeg[t] = 0;
    scnt[t] = 0;
    __syncthreads();
    int e64 = se64;

    for (int e = t; e < ETOT; e += NN) {
        int dst = (e < EE) ? (e64 ? edge[2 * (EE + e)] : edge[EE + e]) : (e - EE);
        if (dst >= 0 && dst < NN) atomicAdd(&sdeg[dst], 1);
    }
    __syncthreads();

    ss[t] = sdeg[t];
    __syncthreads();
    for (int off = 1; off < NN; off <<= 1) {
        int v = (t >= off) ? ss[t - off] : 0;
        __syncthreads();
        ss[t] += v;
        __syncthreads();
    }
    srow[t] = ss[t] - sdeg[t];
    g_rowptr[t + 1] = ss[t];
    if (t == 0) g_rowptr[0] = 0;
    __syncthreads();

    for (int e = t; e < ETOT; e += NN) {
        int s, d;
        if (e < EE) {
            s = e64 ? edge[2 * e] : edge[e];
            d = e64 ? edge[2 * (EE + e)] : edge[EE + e];
        } else {
            s = e - EE; d = e - EE;
        }
        if (s < 0 || s >= NN || d < 0 || d >= NN) continue;
        float nm = rsqrtf((float)sdeg[s]) * rsqrtf((float)sdeg[d]);
        int pos = srow[d] + atomicAdd(&scnt[d], 1);
        g_edge[pos] = make_int2(s, __float_as_int(nm));
    }
    __syncthreads();

    float* arow = g_A + (size_t)t * NN;
    for (int i = srow[t]; i < ss[t]; i++) {
        int2 e = g_edge[i];
        arow[e.x] += __int_as_float(e.y);
    }
}

// ---------------- fp16 cp.async GEMM: C[M,N] = Ah[M,256] @ Bp (+bias) ---------
// A: row-major half (128 words/row). B: k-pair-packed [pair][256 n].
// Tiles: A 128x16 words (stride 20), B 16x128 words (stride 136).
#define HA_ST 20
#define HB_ST 136
#define HA_BUF (128 * HA_ST)
#define HB_BUF (16 * HB_ST)

__global__ __launch_bounds__(256) void k_hgemm(
    const uint32_t* __restrict__ Abase,
    const uint32_t* __restrict__ Bbase,
    float* __restrict__ c0p, float* __restrict__ c1p, float* __restrict__ c2p,
    const float* __restrict__ bias)
{
    const int z = blockIdx.z;
    int tid = threadIdx.x;

    if (z == 3) {
        // service: convert dense A fp32 -> fp16 pairs (post-k_graph)
        int cta = blockIdx.x * 128 + blockIdx.y;    // 0..255
        int i4  = cta * 256 + tid;                  // 65536 float4s
        float4 v = ((const float4*)g_A)[i4];
        uint2 o;
        o.x = h2bits(v.x, v.y);
        o.y = h2bits(v.z, v.w);
        *(uint2*)(g_Ah + (size_t)i4 * 2) = o;
        return;
    }

    __shared__ uint32_t Asb[2 * HA_BUF];
    __shared__ uint32_t Bsb[2 * HB_BUF];
    __shared__ float    bsh[128];

    const uint32_t* A  = Abase + (size_t)z * (BB * NN * 128);
    const uint32_t* Bp = Bbase + (size_t)z * (128 * 256);
    float*          C  = (z == 0) ? c0p : (z == 1) ? c1p : c2p;

    const int n0 = blockIdx.x * 128;
    const int m0 = blockIdx.y * 128;

    int wid  = tid >> 5;
    int lane = tid & 31;
    int grp  = lane >> 2;
    int tig  = lane & 3;
    int wm   = (wid & 1) * 64;
    int wn   = (wid >> 1) * 32;

    if (tid < 128) bsh[tid] = bias ? bias[n0 + tid] : 0.f;

    uint32_t sA = (uint32_t)__cvta_generic_to_shared(Asb);
    uint32_t sB = (uint32_t)__cvta_generic_to_shared(Bsb);

    float acc[4][4][4];
    #pragma unroll
    for (int i = 0; i < 4; i++)
        #pragma unroll
        for (int j = 0; j < 4; j++)
            #pragma unroll
            for (int r = 0; r < 4; r++) acc[i][j][r] = 0.f;

    // prologue chunk 0
    #pragma unroll
    for (int t = 0; t < 2; t++) {
        int i = tid + t * 256;
        int row = i >> 2, q = (i & 3) * 4;
        cp16(sA + (row * HA_ST + q) * 4, A + (size_t)(m0 + row) * 128 + q);
    }
    #pragma unroll
    for (int t = 0; t < 2; t++) {
        int i = tid + t * 256;
        int pr = i >> 5, w = (i & 31) * 4;
        cp16(sB + (pr * HB_ST + w) * 4, Bp + (size_t)pr * 256 + n0 + w);
    }
    CP_COMMIT();

    for (int c = 0; c < 8; c++) {
        CP_WAIT0();
        __syncthreads();

        if (c + 1 < 8) {
            int buf = (c + 1) & 1;
            uint32_t dA = sA + buf * HA_BUF * 4;
            uint32_t dB = sB + buf * HB_BUF * 4;
            int kw = (c + 1) * 16;      // word offset in A row
            int pb = (c + 1) * 16;      // pair base for B
            #pragma unroll
            for (int t = 0; t < 2; t++) {
                int i = tid + t * 256;
                int row = i >> 2, q = (i & 3) * 4;
                cp16(dA + (row * HA_ST + q) * 4,
                     A + (size_t)(m0 + row) * 128 + kw + q);
            }
            #pragma unroll
            for (int t = 0; t < 2; t++) {
                int i = tid + t * 256;
                int pr = i >> 5, w = (i & 31) * 4;
                cp16(dB + (pr * HB_ST + w) * 4,
                     Bp + (size_t)(pb + pr) * 256 + n0 + w);
            }
            CP_COMMIT();
        }

        const uint32_t* As = Asb + (c & 1) * HA_BUF;
        const uint32_t* Bs = Bsb + (c & 1) * HB_BUF;

        #pragma unroll
        for (int s = 0; s < 2; s++) {
            uint32_t af[4][4], bf[4][2];
            #pragma unroll
            for (int mt = 0; mt < 4; mt++) {
                int r = wm + mt * 16 + grp;
                af[mt][0] = As[r * HA_ST + 8 * s + tig];
                af[mt][1] = As[(r + 8) * HA_ST + 8 * s + tig];
                af[mt][2] = As[r * HA_ST + 8 * s + tig + 4];
                af[mt][3] = As[(r + 8) * HA_ST + 8 * s + tig + 4];
            }
            #pragma unroll
            for (int nt = 0; nt < 4; nt++) {
                int cc = wn + nt * 8 + grp;
                bf[nt][0] = Bs[(8 * s + tig) * HB_ST + cc];
                bf[nt][1] = Bs[(8 * s + tig + 4) * HB_ST + cc];
            }
            #pragma unroll
            for (int mt = 0; mt < 4; mt++)
                #pragma unroll
                for (int nt = 0; nt < 4; nt++)
                    mma_f16(acc[mt][nt], af[mt], bf[nt][0], bf[nt][1]);
        }
        __syncthreads();
    }

    #pragma unroll
    for (int mt = 0; mt < 4; mt++) {
        #pragma unroll
        for (int nt = 0; nt < 4; nt++) {
            int cc = wn + nt * 8 + tig * 2;
            float b0 = bsh[cc], b1 = bsh[cc + 1];
            size_t r0 = (size_t)(m0 + wm + mt * 16 + grp) * 256 + n0 + cc;
            size_t r1 = r0 + 8 * 256;
            float2 v0 = {acc[mt][nt][0] + b0, acc[mt][nt][1] + b1};
            float2 v1 = {acc[mt][nt][2] + b0, acc[mt][nt][3] + b1};
            *(float2*)(C + r0) = v0;
            *(float2*)(C + r1) = v1;
        }
    }
}

// ---------------- xw -> fp16 pairs (k_vh pattern) -----------------------------
__global__ void k_xwp() {
    int z   = blockIdx.y;
    int idx = blockIdx.x * 256 + threadIdx.x;     // 524288
    int dq = (idx & 63) * 4;
    int p  = (idx >> 6) & 255;
    int b  = idx >> 14;
    const float* X = (z == 0) ? g_xwq : (z == 1) ? g_xwk : g_xwv;
    const float* v0 = X + ((size_t)b * NN + 2 * p) * DD + dq;
    float4 x0 = *(const float4*)v0;
    float4 x1 = *(const float4*)(v0 + DD);
    uint4 o;
    o.x = h2bits(x0.x, x1.x);
    o.y = h2bits(x0.y, x1.y);
    o.z = h2bits(x0.z, x1.z);
    o.w = h2bits(x0.w, x1.w);
    *(uint4*)(g_xwP + (size_t)z * 2097152 + ((size_t)(b * 256 + p) * 256 + dq)) = o;
}

// ---------------- fp16 aggregation GEMM: out = Ah @ xwP (+bias, tf32 round) ---
__global__ __launch_bounds__(256) void k_agg_h(
    const float* __restrict__ bq, const float* __restrict__ bk,
    const float* __restrict__ bv,
    float* __restrict__ oq, float* __restrict__ ok_, float* __restrict__ ov)
{
    __shared__ uint32_t Asb[2 * HA_BUF];
    __shared__ uint32_t Bsb[2 * HB_BUF];
    __shared__ float    bsh[128];

    int zz = blockIdx.z;
    int z  = zz >> 5;
    int b  = zz & 31;
    const float* bias = (z == 0) ? bq : (z == 1) ? bk : bv;
    float*       O    = (z == 0) ? oq : (z == 1) ? ok_ : ov;
    const uint32_t* Bp = g_xwP + (size_t)z * 2097152 + (size_t)b * 65536;
    float* Cb = O + (size_t)b * NN * DD;

    const int n0 = blockIdx.x * 128;
    const int m0 = blockIdx.y * 128;

    int tid  = threadIdx.x;
    int wid  = tid >> 5;
    int lane = tid & 31;
    int grp  = lane >> 2;
    int tig  = lane & 3;
    int wm   = (wid & 1) * 64;
    int wn   = (wid >> 1) * 32;

    if (tid < 128) bsh[tid] = bias[n0 + tid];

    uint32_t sA = (uint32_t)__cvta_generic_to_shared(Asb);
    uint32_t sB = (uint32_t)__cvta_generic_to_shared(Bsb);

    float acc[4][4][4];
    #pragma unroll
    for (int i = 0; i < 4; i++)
        #pragma unroll
        for (int j = 0; j < 4; j++)
            #pragma unroll
            for (int r = 0; r < 4; r++) acc[i][j][r] = 0.f;

    #pragma unroll
    for (int t = 0; t < 2; t++) {
        int i = tid + t * 256;
        int row = i >> 2, q = (i & 3) * 4;
        cp16(sA + (row * HA_ST + q) * 4, g_Ah + (size_t)(m0 + row) * 256 + q);
    }
    #pragma unroll
    for (int t = 0; t < 2; t++) {
        int i = tid + t * 256;
        int pr = i >> 5, w = (i & 31) * 4;
        cp16(sB + (pr * HB_ST + w) * 4, Bp + (size_t)pr * 256 + n0 + w);
    }
    CP_COMMIT();

    for (int c = 0; c < 16; c++) {
        CP_WAIT0();
        __syncthreads();

        if (c + 1 < 16) {
            int buf = (c + 1) & 1;
            uint32_t dA = sA + buf * HA_BUF * 4;
            uint32_t dB = sB + buf * HB_BUF * 4;
            int kw = (c + 1) * 16;
            int pb = (c + 1) * 16;
            #pragma unroll
            for (int t = 0; t < 2; t++) {
                int i = tid + t * 256;
                int row = i >> 2, q = (i & 3) * 4;
                cp16(dA + (row * HA_ST + q) * 4,
                     g_Ah + (size_t)(m0 + row) * 256 + kw + q);
            }
            #pragma unroll
            for (int t = 0; t < 2; t++) {
                int i = tid + t * 256;
                int pr = i >> 5, w = (i & 31) * 4;
                cp16(dB + (pr * HB_ST + w) * 4,
                     Bp + (size_t)(pb + pr) * 256 + n0 + w);
            }
            CP_COMMIT();
        }

        const uint32_t* As = Asb + (c & 1) * HA_BUF;
        const uint32_t* Bs = Bsb + (c & 1) * HB_BUF;

        #pragma unroll
        for (int s = 0; s < 2; s++) {
            uint32_t af[4][4], bf[4][2];
            #pragma unroll
            for (int mt = 0; mt < 4; mt++) {
                int r = wm + mt * 16 + grp;
                af[mt][0] = As[r * HA_ST + 8 * s + tig];
                af[mt][1] = As[(r + 8) * HA_ST + 8 * s + tig];
                af[mt][2] = As[r * HA_ST + 8 * s + tig + 4];
                af[mt][3] = As[(r + 8) * HA_ST + 8 * s + tig + 4];
            }
            #pragma unroll
            for (int nt = 0; nt < 4; nt++) {
                int cc = wn + nt * 8 + grp;
                bf[nt][0] = Bs[(8 * s + tig) * HB_ST + cc];
                bf[nt][1] = Bs[(8 * s + tig + 4) * HB_ST + cc];
            }
            #pragma unroll
            for (int mt = 0; mt < 4; mt++)
                #pragma unroll
                for (int nt = 0; nt < 4; nt++)
                    mma_f16(acc[mt][nt], af[mt], bf[nt][0], bf[nt][1]);
        }
        __syncthreads();
    }

    // epilogue: bias + tf32-round (attention raw-loads these as tf32)
    #pragma unroll
    for (int mt = 0; mt < 4; mt++) {
        #pragma unroll
        for (int nt = 0; nt < 4; nt++) {
            int cc = wn + nt * 8 + tig * 2;
            float b0 = bsh[cc], b1 = bsh[cc + 1];
            size_t r0 = (size_t)(m0 + wm + mt * 16 + grp) * 256 + n0 + cc;
            size_t r1 = r0 + 8 * 256;
            float2 v0, v1;
            v0.x = __uint_as_float(f2tf32(acc[mt][nt][0] + b0));
            v0.y = __uint_as_float(f2tf32(acc[mt][nt][1] + b1));
            v1.x = __uint_as_float(f2tf32(acc[mt][nt][2] + b0));
            v1.y = __uint_as_float(f2tf32(acc[mt][nt][3] + b1));
            *(float2*)(Cb + r0) = v0;
            *(float2*)(Cb + r1) = v1;
        }
    }
}

// ---------------- V -> half2-paired copy (g_V -> g_Vh) ------------------------
__global__ void k_vh() {
    int idx = blockIdx.x * 256 + threadIdx.x;
    int dq = (idx & 63) * 4;
    int p  = (idx >> 6) & 255;
    int b  = idx >> 14;
    const float* v0 = g_V + ((size_t)b * NN + 2 * p) * DD + dq;
    float4 x0 = *(const float4*)v0;
    float4 x1 = *(const float4*)(v0 + DD);
    uint4 o;
    o.x = h2bits(x0.x, x1.x);
    o.y = h2bits(x0.y, x1.y);
    o.z = h2bits(x0.z, x1.z);
    o.w = h2bits(x0.w, x1.w);
    *(uint4*)(g_Vh + ((size_t)(b * 256 + p) * 256 + dq)) = o;
}

// ---------------- flash attention: tf32 QK + fp16 PV; half output -------------
#define KW      36
#define KWORDS  (64 * KW)
#define VWORDS  (32 * KW)
#define BUFW    (KWORDS + VWORDS)
#define ATT_SMEM (2 * BUFW * 4)

__global__ __launch_bounds__(256, 2) void k_attn(
    const float* __restrict__ Q, const float* __restrict__ K)
{
    extern __shared__ uint32_t sm[];

    int h   = blockIdx.y;
    int b   = blockIdx.z;
    int tid = threadIdx.x;
    int wid = tid >> 5, lane = tid & 31;
    int grp = lane >> 2, tig = lane & 3;
    int qw  = blockIdx.x * 128 + wid * 16;

    const float* Qb = Q + (size_t)b * NN * DD + h * HDIM;
    const float* Kb = K + (size_t)b * NN * DD + h * HDIM;

    const float escale = 0.17677669529663687f;

    uint32_t qa[4][4];
    #pragma unroll
    for (int kf = 0; kf < 4; kf++) {
        int cl = kf * 8 + tig;
        qa[kf][0] = __float_as_uint(Qb[(size_t)(qw + grp) * DD + cl]);
        qa[kf][1] = __float_as_uint(Qb[(size_t)(qw + grp + 8) * DD + cl]);
        qa[kf][2] = __float_as_uint(Qb[(size_t)(qw + grp) * DD + cl + 4]);
        qa[kf][3] = __float_as_uint(Qb[(size_t)(qw + grp + 8) * DD + cl + 4]);
    }

    float m0 = -3.4e38f, m1 = -3.4e38f, l0 = 0.f, l1 = 0.f;
    float oacc[4][4];
    #pragma unroll
    for (int nt = 0; nt < 4; nt++)
        #pragma unroll
        for (int r = 0; r < 4; r++) oacc[nt][r] = 0.f;

    const uint32_t* bm0 = g_bmask + (size_t)(qw + grp) * 16;
    const uint32_t* bm1 = g_bmask + (size_t)(qw + grp + 8) * 16;

    uint32_t sbase = (uint32_t)__cvta_generic_to_shared(sm);
    int vp = tid >> 3, vq = (tid & 7) * 4;

    #pragma unroll
    for (int t = 0; t < 2; t++) {
        int i = tid + t * 256;
        int r = i >> 3, f = (i & 7) * 4;
        cp16(sbase + (r * KW + f) * 4, Kb + (size_t)r * DD + f);
    }
    cp16(sbase + (KWORDS + vp * KW + vq) * 4,
         g_Vh + (size_t)(b * 256 + vp) * 256 + h * HDIM + vq);
    CP_COMMIT();

    for (int ci = 0; ci < 8; ci++) {
        CP_WAIT0();
        __syncthreads();

        if (ci + 1 < 8) {
            int c1  = (ci + 1) * 64;
            uint32_t dst = sbase + ((ci + 1) & 1) * BUFW * 4;
            #pragma unroll
            for (int t = 0; t < 2; t++) {
                int i = tid + t * 256;
                int r = i >> 3, f = (i & 7) * 4;
                cp16(dst + (r * KW + f) * 4, Kb + (size_t)(c1 + r) * DD + f);
            }
            cp16(dst + (KWORDS + vp * KW + vq) * 4,
                 g_Vh + (size_t)(b * 256 + (ci + 1) * 32 + vp) * 256 + h * HDIM + vq);
            CP_COMMIT();
        }

        const uint32_t* Ks = sm + (ci & 1) * BUFW;
        const uint32_t* Vs = Ks + KWORDS;
        int c0 = ci * 64;

        float sacc[8][4];
        #pragma unroll
        for (int nt = 0; nt < 8; nt++)
            #pragma unroll
            for (int r = 0; r < 4; r++) sacc[nt][r] = 0.f;
        #pragma unroll
        for (int nt = 0; nt < 8; nt++)
            #pragma unroll
            for (int kf = 0; kf < 4; kf++) {
                uint32_t b0v = Ks[(nt * 8 + grp) * KW + kf * 8 + tig];
                uint32_t b1v = Ks[(nt * 8 + grp) * KW + kf * 8 + tig + 4];
                mma_tf32(sacc[nt], qa[kf], b0v, b1v);
            }

        uint32_t wa0 = bm0[c0 >> 5], wa1 = bm0[(c0 >> 5) + 1];
        uint32_t wb0 = bm1[c0 >> 5], wb1 = bm1[(c0 >> 5) + 1];
        float cm0 = -3.4e38f, cm1 = -3.4e38f;
        #pragma unroll
        for (int nt = 0; nt < 8; nt++) {
            int j  = nt * 8 + 2 * tig;
            uint32_t wa = (j < 32) ? wa0 : wa1;
            uint32_t wb = (j < 32) ? wb0 : wb1;
            int sh = j & 31;
            if (!((wa >> sh) & 1))        sacc[nt][0] = -1e10f;
            if (!((wa >> (sh + 1)) & 1))  sacc[nt][1] = -1e10f;
            if (!((wb >> sh) & 1))        sacc[nt][2] = -1e10f;
            if (!((wb >> (sh + 1)) & 1))  sacc[nt][3] = -1e10f;
            cm0 = fmaxf(cm0, fmaxf(sacc[nt][0], sacc[nt][1]));
            cm1 = fmaxf(cm1, fmaxf(sacc[nt][2], sacc[nt][3]));
        }
        cm0 = fmaxf(cm0, __shfl_xor_sync(0xffffffffu, cm0, 1));
        cm0 = fmaxf(cm0, __shfl_xor_sync(0xffffffffu, cm0, 2));
        cm1 = fmaxf(cm1, __shfl_xor_sync(0xffffffffu, cm1, 1));
        cm1 = fmaxf(cm1, __shfl_xor_sync(0xffffffffu, cm1, 2));

        float nm0 = fmaxf(m0, cm0), nm1 = fmaxf(m1, cm1);
        float f0 = __expf((m0 - nm0) * escale), f1 = __expf((m1 - nm1) * escale);
        l0 *= f0; l1 *= f1;
        #pragma unroll
        for (int nt = 0; nt < 4; nt++) {
            oacc[nt][0] *= f0; oacc[nt][1] *= f0;
            oacc[nt][2] *= f1; oacc[nt][3] *= f1;
        }
        m0 = nm0; m1 = nm1;

        uint32_t h2a[8], h2b[8];
        #pragma unroll
        for (int nt = 0; nt < 8; nt++) {
            float p0 = __expf((sacc[nt][0] - nm0) * escale);
            float p1 = __expf((sacc[nt][1] - nm0) * escale);
            float p2 = __expf((sacc[nt][2] - nm1) * escale);
            float p3 = __expf((sacc[nt][3] - nm1) * escale);
            l0 += p0 + p1; l1 += p2 + p3;
            h2a[nt] = h2bits(p0, p1);
            h2b[nt] = h2bits(p2, p3);
        }

        #pragma unroll
        for (int s = 0; s < 4; s++) {
            uint32_t pa[4];
            pa[0] = h2a[2 * s];
            pa[1] = h2b[2 * s];
            pa[2] = h2a[2 * s + 1];
            pa[3] = h2b[2 * s + 1];
            #pragma unroll
            for (int nt = 0; nt < 4; nt++) {
                uint32_t b0v = Vs[(s * 8 + tig) * KW + nt * 8 + grp];
                uint32_t b1v = Vs[(s * 8 + tig + 4) * KW + nt * 8 + grp];
                mma_f16(oacc[nt], pa, b0v, b1v);
            }
        }
    }

    l0 += __shfl_xor_sync(0xffffffffu, l0, 1);
    l0 += __shfl_xor_sync(0xffffffffu, l0, 2);
    l1 += __shfl_xor_sync(0xffffffffu, l1, 1);
    l1 += __shfl_xor_sync(0xffffffffu, l1, 2);
    float inv0 = 1.f / l0, inv1 = 1.f / l1;

    // epilogue: normalize -> fp16 att (row-major pairs along d)
    uint32_t* o0 = g_atth + (size_t)(b * NN + qw + grp) * 128 + h * 16;
    uint32_t* o1 = g_atth + (size_t)(b * NN + qw + grp + 8) * 128 + h * 16;
    #pragma unroll
    for (int nt = 0; nt < 4; nt++) {
        o0[nt * 4 + tig] = h2bits(oacc[nt][0] * inv0, oacc[nt][1] * inv0);
        o1[nt * 4 + tig] = h2bits(oacc[nt][2] * inv1, oacc[nt][3] * inv1);
    }
}

// ---------------- launch ------------------------------------------------------
extern "C" void kernel_launch(void* const* d_in, const int* in_sizes, int n_in,
                              void* d_out, int out_size) {
    const float* query = (const float*)d_in[0];
    const float* key   = (const float*)d_in[1];
    const float* value = (const float*)d_in[2];
    const int*   edge  = (const int*)d_in[3];
    const int*   mask  = (const int*)d_in[4];
    const float* Wq = (const float*)d_in[5];
    const float* bq = (const float*)d_in[6];
    const float* Wk = (const float*)d_in[7];
    const float* bk = (const float*)d_in[8];
    const float* Wv = (const float*)d_in[9];
    const float* bv = (const float*)d_in[10];
    const float* Wo = (const float*)d_in[11];
    const float* bo = (const float*)d_in[12];
    float* out = (float*)d_out;

    float *xwq, *xwk, *xwv, *Qp, *Kp, *Vp;
    uint32_t *Xh, *Wp, *atth;
    cudaGetSymbolAddress((void**)&xwq, g_xwq);
    cudaGetSymbolAddress((void**)&xwk, g_xwk);
    cudaGetSymbolAddress((void**)&xwv, g_xwv);
    cudaGetSymbolAddress((void**)&Qp,  g_Q);
    cudaGetSymbolAddress((void**)&Kp,  g_K);
    cudaGetSymbolAddress((void**)&Vp,  g_V);
    cudaGetSymbolAddress((void**)&Xh,  g_Xh);
    cudaGetSymbolAddress((void**)&Wp,  g_Wp);
    cudaGetSymbolAddress((void**)&atth, g_atth);

    cudaFuncSetAttribute(k_attn, cudaFuncAttributeMaxDynamicSharedMemorySize,
                         ATT_SMEM);

    // 1: inputs->fp16, W->fp16 pairs, zero A, pack mask
    k_round<<<2048, 256>>>(query, key, value, Wq, Wk, Wv, Wo, mask);

    // 2: graph prep + dense adjacency fill (single CTA)
    k_graph<<<1, NN>>>(edge);

    // 3: QKV projection (fp16 MMA; z=3 service: A fp32 -> fp16)
    k_hgemm<<<dim3(2, 128, 4), 256>>>(Xh, Wp, xwq, xwk, xwv, nullptr);

    // 4: xw -> fp16 pairs
    k_xwp<<<dim3(2048, 3), 256>>>();

    // 5: aggregation GEMM (fp16 MMA; +bias, tf32-rounded outputs)
    k_agg_h<<<dim3(2, 4, 96), 256>>>(bq, bk, bv, Qp, Kp, Vp);

    // 6: pair V into half2
    k_vh<<<2048, 256>>>();

    // 7: flash attention (tf32 QK + fp16 PV) -> fp16 att
    k_attn<<<dim3(4, HH, BB), 256, ATT_SMEM>>>(Qp, Kp);

    // 8: output projection (fp16 MMA; +bias, fp32) into d_out
    k_hgemm<<<dim3(2, 128, 1), 256>>>(atth, Wp + 3 * 128 * 256,
                                      out, out, out, bo);
}

// round 16
// speedup vs baseline: 1.2796x; 1.0443x over previous
#include <cuda_runtime.h>
#include <cuda_fp16.h>
#include <cstdint>

#define BB   32
#define NN   512
#define DD   256
#define HH   8
#define HDIM 32
#define EE   16384
#define ETOT (EE + NN)

// ---------------- scratch (static device globals; no allocation) -------------
__device__ float    g_Q  [BB * NN * DD];
__device__ float    g_K  [BB * NN * DD];
__device__ int      g_rowptr[NN + 1];
__device__ int2     g_edge[ETOT];
__device__ uint32_t g_bmask[NN * 16];
__device__ float    g_A[NN * NN];                 // fp32 adjacency (built once)
__device__ uint32_t g_Ah[NN * 256];               // fp16 adjacency, row-major pairs
__device__ uint32_t g_Xh[3 * BB * NN * 128];      // fp16 q/k/v inputs row-major
__device__ uint32_t g_Wp[4 * 128 * 256];          // fp16 W k-pair-packed [pair][n]
__device__ uint32_t g_xwP[3 * BB * 256 * 256];    // fp16 xw k-pair-packed
__device__ uint32_t g_Vh[BB * 256 * 256];         // fp16 V pairs (attention PV)
__device__ uint32_t g_atth[BB * NN * 128];        // fp16 attention output

// ---------------- helpers -----------------------------------------------------
__device__ __forceinline__ uint32_t f2tf32(float f) {
    uint32_t r;
    asm("cvt.rna.tf32.f32 %0, %1;" : "=r"(r) : "f"(f));
    return r;
}
__device__ __forceinline__ void mma_tf32(float* c, const uint32_t* a,
                                         uint32_t b0, uint32_t b1) {
    asm volatile(
        "mma.sync.aligned.m16n8k8.row.col.f32.tf32.tf32.f32 "
        "{%0,%1,%2,%3}, {%4,%5,%6,%7}, {%8,%9}, {%0,%1,%2,%3};"
        : "+f"(c[0]), "+f"(c[1]), "+f"(c[2]), "+f"(c[3])
        : "r"(a[0]), "r"(a[1]), "r"(a[2]), "r"(a[3]), "r"(b0), "r"(b1));
}
__device__ __forceinline__ void mma_f16(float* c, const uint32_t* a,
                                        uint32_t b0, uint32_t b1) {
    asm volatile(
        "mma.sync.aligned.m16n8k16.row.col.f32.f16.f16.f32 "
        "{%0,%1,%2,%3}, {%4,%5,%6,%7}, {%8,%9}, {%0,%1,%2,%3};"
        : "+f"(c[0]), "+f"(c[1]), "+f"(c[2]), "+f"(c[3])
        : "r"(a[0]), "r"(a[1]), "r"(a[2]), "r"(a[3]), "r"(b0), "r"(b1));
}
__device__ __forceinline__ uint32_t h2bits(float a, float b) {
    __half2 h = __floats2half2_rn(a, b);
    return *reinterpret_cast<uint32_t*>(&h);
}
__device__ __forceinline__ void cp16(uint32_t saddr, const void* g) {
    asm volatile("cp.async.ca.shared.global [%0], [%1], 16;"
                 :: "r"(saddr), "l"(g) : "memory");
}
#define CP_COMMIT() asm volatile("cp.async.commit_group;" ::: "memory")
#define CP_WAIT0()  asm volatile("cp.async.wait_group 0;" ::: "memory")

// ---------------- prep: inputs->fp16, W->fp16 pairs, zero A, pack mask --------
__global__ void k_round(const float* __restrict__ q, const float* __restrict__ k,
                        const float* __restrict__ v,
                        const float* __restrict__ wq, const float* __restrict__ wk,
                        const float* __restrict__ wv, const float* __restrict__ wo,
                        const int* __restrict__ mask) {
    int idx = blockIdx.x * 256 + threadIdx.x;
    #pragma unroll
    for (int t = 0; t < 6; t++) {
        int i = idx + t * 524288;
        int j   = i >> 20;
        int off = i & 0xFFFFF;
        const float4* s = (j == 0) ? (const float4*)q
                        : (j == 1) ? (const float4*)k : (const float4*)v;
        float4 x = s[off];
        uint2 o;
        o.x = h2bits(x.x, x.y);
        o.y = h2bits(x.z, x.w);
        *(uint2*)(g_Xh + (size_t)j * 2097152 + (size_t)off * 2) = o;
    }
    if (idx < 65536) {
        int j   = idx >> 14;
        int rem = idx & 16383;
        int p   = rem >> 7;
        int n2  = (rem & 127) * 2;
        const float* w = (j == 0) ? wq : (j == 1) ? wk : (j == 2) ? wv : wo;
        float2 e = *(const float2*)(w + (size_t)(2 * p) * 256 + n2);
        float2 o = *(const float2*)(w + (size_t)(2 * p + 1) * 256 + n2);
        uint2 u;
        u.x = h2bits(e.x, o.x);
        u.y = h2bits(e.y, o.y);
        *(uint2*)(g_Wp + (size_t)(j * 128 + p) * 256 + n2) = u;
        ((float4*)g_A)[idx] = make_float4(0.f, 0.f, 0.f, 0.f);
    }
    if (idx < NN * 16) {
        int r  = idx >> 4;
        int wd = idx & 15;
        const int* mrow = mask + (size_t)r * NN + wd * 32;
        uint32_t bits = 0;
        #pragma unroll
        for (int jb = 0; jb < 32; jb++) bits |= (mrow[jb] ? 1u : 0u) << jb;
        g_bmask[idx] = bits;
    }
}

// ---------------- fused single-CTA graph prep + dense A fill ------------------
__global__ __launch_bounds__(NN) void k_graph(const int* __restrict__ edge) {
    __shared__ int sdeg[NN];
    __shared__ int scnt[NN];
    __shared__ int srow[NN];
    __shared__ int ss[NN];
    __shared__ int se64;
    int t = threadIdx.x;

    if (t == 0) {
        int nz = 0;
        for (int i = 0; i < 64; i++) nz += (edge[2 * i + 1] != 0);
        se64 = (nz == 0) ? 1 : 0;
    }
    sdeg[t] = 0;
    scnt[t] = 0;
    __syncthreads();
    int e64 = se64;

    for (int e = t; e < ETOT; e += NN) {
        int dst = (e < EE) ? (e64 ? edge[2 * (EE + e)] : edge[EE + e]) : (e - EE);
        if (dst >= 0 && dst < NN) atomicAdd(&sdeg[dst], 1);
    }
    __syncthreads();

    ss[t] = sdeg[t];
    __syncthreads();
    for (int off = 1; off < NN; off <<= 1) {
        int v = (t >= off) ? ss[t - off] : 0;
        __syncthreads();
        ss[t] += v;
        __syncthreads();
    }
    srow[t] = ss[t] - sdeg[t];
    g_rowptr[t + 1] = ss[t];
    if (t == 0) g_rowptr[0] = 0;
    __syncthreads();

    for (int e = t; e < ETOT; e += NN) {
        int s, d;
        if (e < EE) {
            s = e64 ? edge[2 * e] : edge[e];
            d = e64 ? edge[2 * (EE + e)] : edge[EE + e];
        } else {
            s = e - EE; d = e - EE;
        }
        if (s < 0 || s >= NN || d < 0 || d >= NN) continue;
        float nm = rsqrtf((float)sdeg[s]) * rsqrtf((float)sdeg[d]);
        int pos = srow[d] + atomicAdd(&scnt[d], 1);
        g_edge[pos] = make_int2(s, __float_as_int(nm));
    }
    __syncthreads();

    float* arow = g_A + (size_t)t * NN;
    for (int i = srow[t]; i < ss[t]; i++) {
        int2 e = g_edge[i];
        arow[e.x] += __int_as_float(e.y);
    }
}

// ---------------- fp16 cp.async GEMM ------------------------------------------
// A: row-major half (128 words/row). B: k-pair-packed [pair][256 n].
// packC=1: write fp16 m-pair-packed into g_xwP[z] (no bias).
// packC=0: write fp32 +bias to C (output projection).
#define HA_ST 20
#define HB_ST 136
#define HA_BUF (128 * HA_ST)
#define HB_BUF (16 * HB_ST)

__global__ __launch_bounds__(256) void k_hgemm(
    const uint32_t* __restrict__ Abase,
    const uint32_t* __restrict__ Bbase,
    float* __restrict__ Cout,
    const float* __restrict__ bias, int packC)
{
    const int z = blockIdx.z;
    int tid = threadIdx.x;

    if (z == 3) {
        // service: dense A fp32 -> fp16 pairs (post-k_graph)
        int cta = blockIdx.x * 128 + blockIdx.y;
        int i4  = cta * 256 + tid;
        float4 v = ((const float4*)g_A)[i4];
        uint2 o;
        o.x = h2bits(v.x, v.y);
        o.y = h2bits(v.z, v.w);
        *(uint2*)(g_Ah + (size_t)i4 * 2) = o;
        return;
    }

    __shared__ uint32_t Asb[2 * HA_BUF];
    __shared__ uint32_t Bsb[2 * HB_BUF];
    __shared__ float    bsh[128];

    const uint32_t* A  = Abase + (size_t)z * (BB * NN * 128);
    const uint32_t* Bp = Bbase + (size_t)z * (128 * 256);

    const int n0 = blockIdx.x * 128;
    const int m0 = blockIdx.y * 128;

    int wid  = tid >> 5;
    int lane = tid & 31;
    int grp  = lane >> 2;
    int tig  = lane & 3;
    int wm   = (wid & 1) * 64;
    int wn   = (wid >> 1) * 32;

    if (tid < 128) bsh[tid] = bias ? bias[n0 + tid] : 0.f;

    uint32_t sA = (uint32_t)__cvta_generic_to_shared(Asb);
    uint32_t sB = (uint32_t)__cvta_generic_to_shared(Bsb);

    float acc[4][4][4];
    #pragma unroll
    for (int i = 0; i < 4; i++)
        #pragma unroll
        for (int j = 0; j < 4; j++)
            #pragma unroll
            for (int r = 0; r < 4; r++) acc[i][j][r] = 0.f;

    #pragma unroll
    for (int t = 0; t < 2; t++) {
        int i = tid + t * 256;
        int row = i >> 2, q = (i & 3) * 4;
        cp16(sA + (row * HA_ST + q) * 4, A + (size_t)(m0 + row) * 128 + q);
    }
    #pragma unroll
    for (int t = 0; t < 2; t++) {
        int i = tid + t * 256;
        int pr = i >> 5, w = (i & 31) * 4;
        cp16(sB + (pr * HB_ST + w) * 4, Bp + (size_t)pr * 256 + n0 + w);
    }
    CP_COMMIT();

    for (int c = 0; c < 8; c++) {
        CP_WAIT0();
        __syncthreads();

        if (c + 1 < 8) {
            int buf = (c + 1) & 1;
            uint32_t dA = sA + buf * HA_BUF * 4;
            uint32_t dB = sB + buf * HB_BUF * 4;
            int kw = (c + 1) * 16;
            int pb = (c + 1) * 16;
            #pragma unroll
            for (int t = 0; t < 2; t++) {
                int i = tid + t * 256;
                int row = i >> 2, q = (i & 3) * 4;
                cp16(dA + (row * HA_ST + q) * 4,
                     A + (size_t)(m0 + row) * 128 + kw + q);
            }
            #pragma unroll
            for (int t = 0; t < 2; t++) {
                int i = tid + t * 256;
                int pr = i >> 5, w = (i & 31) * 4;
                cp16(dB + (pr * HB_ST + w) * 4,
                     Bp + (size_t)(pb + pr) * 256 + n0 + w);
            }
            CP_COMMIT();
        }

        const uint32_t* As = Asb + (c & 1) * HA_BUF;
        const uint32_t* Bs = Bsb + (c & 1) * HB_BUF;

        #pragma unroll
        for (int s = 0; s < 2; s++) {
            uint32_t af[4][4], bf[4][2];
            #pragma unroll
            for (int mt = 0; mt < 4; mt++) {
                int r = wm + mt * 16 + grp;
                af[mt][0] = As[r * HA_ST + 8 * s + tig];
                af[mt][1] = As[(r + 8) * HA_ST + 8 * s + tig];
                af[mt][2] = As[r * HA_ST + 8 * s + tig + 4];
                af[mt][3] = As[(r + 8) * HA_ST + 8 * s + tig + 4];
            }
            #pragma unroll
            for (int nt = 0; nt < 4; nt++) {
                int cc = wn + nt * 8 + grp;
                bf[nt][0] = Bs[(8 * s + tig) * HB_ST + cc];
                bf[nt][1] = Bs[(8 * s + tig + 4) * HB_ST + cc];
            }
            #pragma unroll
            for (int mt = 0; mt < 4; mt++)
                #pragma unroll
                for (int nt = 0; nt < 4; nt++)
                    mma_f16(acc[mt][nt], af[mt], bf[nt][0], bf[nt][1]);
        }
        __syncthreads();
    }

    if (packC) {
        // pair adjacent m-rows via shfl_xor(4); even-grp lanes store half2 words
        int b = m0 >> 9;
        uint32_t* dst = g_xwP + (size_t)z * 2097152 + (size_t)b * 65536;
        #pragma unroll
        for (int mt = 0; mt < 4; mt++) {
            #pragma unroll
            for (int nt = 0; nt < 4; nt++) {
                int cc = n0 + wn + nt * 8 + tig * 2;
                float a0 = acc[mt][nt][0], a1 = acc[mt][nt][1];
                float a2 = acc[mt][nt][2], a3 = acc[mt][nt][3];
                float p0 = __shfl_xor_sync(0xffffffffu, a0, 4);
                float p1 = __shfl_xor_sync(0xffffffffu, a1, 4);
                float p2 = __shfl_xor_sync(0xffffffffu, a2, 4);
                float p3 = __shfl_xor_sync(0xffffffffu, a3, 4);
                if (!(grp & 1)) {
                    int r0 = (m0 & 511) + wm + mt * 16 + grp;
                    uint2 w0 = {h2bits(a0, p0), h2bits(a1, p1)};
                    uint2 w1 = {h2bits(a2, p2), h2bits(a3, p3)};
                    *(uint2*)(dst + (size_t)(r0 >> 1) * 256 + cc) = w0;
                    *(uint2*)(dst + (size_t)((r0 + 8) >> 1) * 256 + cc) = w1;
                }
            }
        }
    } else {
        #pragma unroll
        for (int mt = 0; mt < 4; mt++) {
            #pragma unroll
            for (int nt = 0; nt < 4; nt++) {
                int cc = wn + nt * 8 + tig * 2;
                float b0 = bsh[cc], b1 = bsh[cc + 1];
                size_t r0 = (size_t)(m0 + wm + mt * 16 + grp) * 256 + n0 + cc;
                size_t r1 = r0 + 8 * 256;
                float2 v0 = {acc[mt][nt][0] + b0, acc[mt][nt][1] + b1};
                float2 v1 = {acc[mt][nt][2] + b0, acc[mt][nt][3] + b1};
                *(float2*)(Cout + r0) = v0;
                *(float2*)(Cout + r1) = v1;
            }
        }
    }
}

// ---------------- fp16 aggregation GEMM ---------------------------------------
// z=0/1: tf32-rounded fp32 Q/K.  z=2: fp16 kv-pair-packed g_Vh directly.
__global__ __launch_bounds__(256) void k_agg_h(
    const float* __restrict__ bq, const float* __restrict__ bk,
    const float* __restrict__ bv,
    float* __restrict__ oq, float* __restrict__ ok_)
{
    __shared__ uint32_t Asb[2 * HA_BUF];
    __shared__ uint32_t Bsb[2 * HB_BUF];
    __shared__ float    bsh[128];

    int zz = blockIdx.z;
    int z  = zz >> 5;
    int b  = zz & 31;
    const float* bias = (z == 0) ? bq : (z == 1) ? bk : bv;
    const uint32_t* Bp = g_xwP + (size_t)z * 2097152 + (size_t)b * 65536;

    const int n0 = blockIdx.x * 128;
    const int m0 = blockIdx.y * 128;

    int tid  = threadIdx.x;
    int wid  = tid >> 5;
    int lane = tid & 31;
    int grp  = lane >> 2;
    int tig  = lane & 3;
    int wm   = (wid & 1) * 64;
    int wn   = (wid >> 1) * 32;

    if (tid < 128) bsh[tid] = bias[n0 + tid];

    uint32_t sA = (uint32_t)__cvta_generic_to_shared(Asb);
    uint32_t sB = (uint32_t)__cvta_generic_to_shared(Bsb);

    float acc[4][4][4];
    #pragma unroll
    for (int i = 0; i < 4; i++)
        #pragma unroll
        for (int j = 0; j < 4; j++)
            #pragma unroll
            for (int r = 0; r < 4; r++) acc[i][j][r] = 0.f;

    #pragma unroll
    for (int t = 0; t < 2; t++) {
        int i = tid + t * 256;
        int row = i >> 2, q = (i & 3) * 4;
        cp16(sA + (row * HA_ST + q) * 4, g_Ah + (size_t)(m0 + row) * 256 + q);
    }
    #pragma unroll
    for (int t = 0; t < 2; t++) {
        int i = tid + t * 256;
        int pr = i >> 5, w = (i & 31) * 4;
        cp16(sB + (pr * HB_ST + w) * 4, Bp + (size_t)pr * 256 + n0 + w);
    }
    CP_COMMIT();

    for (int c = 0; c < 16; c++) {
        CP_WAIT0();
        __syncthreads();

        if (c + 1 < 16) {
            int buf = (c + 1) & 1;
            uint32_t dA = sA + buf * HA_BUF * 4;
            uint32_t dB = sB + buf * HB_BUF * 4;
            int kw = (c + 1) * 16;
            int pb = (c + 1) * 16;
            #pragma unroll
            for (int t = 0; t < 2; t++) {
                int i = tid + t * 256;
                int row = i >> 2, q = (i & 3) * 4;
                cp16(dA + (row * HA_ST + q) * 4,
                     g_Ah + (size_t)(m0 + row) * 256 + kw + q);
            }
            #pragma unroll
            for (int t = 0; t < 2; t++) {
                int i = tid + t * 256;
                int pr = i >> 5, w = (i & 31) * 4;
                cp16(dB + (pr * HB_ST + w) * 4,
                     Bp + (size_t)(pb + pr) * 256 + n0 + w);
            }
            CP_COMMIT();
        }

        const uint32_t* As = Asb + (c & 1) * HA_BUF;
        const uint32_t* Bs = Bsb + (c & 1) * HB_BUF;

        #pragma unroll
        for (int s = 0; s < 2; s++) {
            uint32_t af[4][4], bf[4][2];
            #pragma unroll
            for (int mt = 0; mt < 4; mt++) {
                int r = wm + mt * 16 + grp;
                af[mt][0] = As[r * HA_ST + 8 * s + tig];
                af[mt][1] = As[(r + 8) * HA_ST + 8 * s + tig];
                af[mt][2] = As[r * HA_ST + 8 * s + tig + 4];
                af[mt][3] = As[(r + 8) * HA_ST + 8 * s + tig + 4];
            }
            #pragma unroll
            for (int nt = 0; nt < 4; nt++) {
                int cc = wn + nt * 8 + grp;
                bf[nt][0] = Bs[(8 * s + tig) * HB_ST + cc];
                bf[nt][1] = Bs[(8 * s + tig + 4) * HB_ST + cc];
            }
            #pragma unroll
            for (int mt = 0; mt < 4; mt++)
                #pragma unroll
                for (int nt = 0; nt < 4; nt++)
                    mma_f16(acc[mt][nt], af[mt], bf[nt][0], bf[nt][1]);
        }
        __syncthreads();
    }

    if (z == 2) {
        // V: pair adjacent kv rows, write fp16 g_Vh directly
        uint32_t* dst = g_Vh + (size_t)b * 65536;
        #pragma unroll
        for (int mt = 0; mt < 4; mt++) {
            #pragma unroll
            for (int nt = 0; nt < 4; nt++) {
                int ccl = wn + nt * 8 + tig * 2;
                int cc  = n0 + ccl;
                float b0 = bsh[ccl], b1 = bsh[ccl + 1];
                float a0 = acc[mt][nt][0] + b0, a1 = acc[mt][nt][1] + b1;
                float a2 = acc[mt][nt][2] + b0, a3 = acc[mt][nt][3] + b1;
                float p0 = __shfl_xor_sync(0xffffffffu, a0, 4);
                float p1 = __shfl_xor_sync(0xffffffffu, a1, 4);
                float p2 = __shfl_xor_sync(0xffffffffu, a2, 4);
                float p3 = __shfl_xor_sync(0xffffffffu, a3, 4);
                if (!(grp & 1)) {
                    int r0 = m0 + wm + mt * 16 + grp;
                    uint2 w0 = {h2bits(a0, p0), h2bits(a1, p1)};
                    uint2 w1 = {h2bits(a2, p2), h2bits(a3, p3)};
                    *(uint2*)(dst + (size_t)(r0 >> 1) * 256 + cc) = w0;
                    *(uint2*)(dst + (size_t)((r0 + 8) >> 1) * 256 + cc) = w1;
                }
            }
        }
    } else {
        float* Cb = ((z == 0) ? oq : ok_) + (size_t)b * NN * DD;
        #pragma unroll
        for (int mt = 0; mt < 4; mt++) {
            #pragma unroll
            for (int nt = 0; nt < 4; nt++) {
                int ccl = wn + nt * 8 + tig * 2;
                float b0 = bsh[ccl], b1 = bsh[ccl + 1];
                size_t r0 = (size_t)(m0 + wm + mt * 16 + grp) * 256 + n0 + ccl;
                size_t r1 = r0 + 8 * 256;
                float2 v0, v1;
                v0.x = __uint_as_float(f2tf32(acc[mt][nt][0] + b0));
                v0.y = __uint_as_float(f2tf32(acc[mt][nt][1] + b1));
                v1.x = __uint_as_float(f2tf32(acc[mt][nt][2] + b0));
                v1.y = __uint_as_float(f2tf32(acc[mt][nt][3] + b1));
                *(float2*)(Cb + r0) = v0;
                *(float2*)(Cb + r1) = v1;
            }
        }
    }
}

// ---------------- flash attention: tf32 QK + fp16 PV; half output -------------
#define KW      36
#define KWORDS  (64 * KW)
#define VWORDS  (32 * KW)
#define BUFW    (KWORDS + VWORDS)
#define ATT_SMEM (2 * BUFW * 4)

__global__ __launch_bounds__(256, 2) void k_attn(
    const float* __restrict__ Q, const float* __restrict__ K)
{
    extern __shared__ uint32_t sm[];

    int h   = blockIdx.y;
    int b   = blockIdx.z;
    int tid = threadIdx.x;
    int wid = tid >> 5, lane = tid & 31;
    int grp = lane >> 2, tig = lane & 3;
    int qw  = blockIdx.x * 128 + wid * 16;

    const float* Qb = Q + (size_t)b * NN * DD + h * HDIM;
    const float* Kb = K + (size_t)b * NN * DD + h * HDIM;

    const float escale = 0.17677669529663687f;

    uint32_t qa[4][4];
    #pragma unroll
    for (int kf = 0; kf < 4; kf++) {
        int cl = kf * 8 + tig;
        qa[kf][0] = __float_as_uint(Qb[(size_t)(qw + grp) * DD + cl]);
        qa[kf][1] = __float_as_uint(Qb[(size_t)(qw + grp + 8) * DD + cl]);
        qa[kf][2] = __float_as_uint(Qb[(size_t)(qw + grp) * DD + cl + 4]);
        qa[kf][3] = __float_as_uint(Qb[(size_t)(qw + grp + 8) * DD + cl + 4]);
    }

    float m0 = -3.4e38f, m1 = -3.4e38f, l0 = 0.f, l1 = 0.f;
    float oacc[4][4];
    #pragma unroll
    for (int nt = 0; nt < 4; nt++)
        #pragma unroll
        for (int r = 0; r < 4; r++) oacc[nt][r] = 0.f;

    const uint32_t* bm0 = g_bmask + (size_t)(qw + grp) * 16;
    const uint32_t* bm1 = g_bmask + (size_t)(qw + grp + 8) * 16;

    uint32_t sbase = (uint32_t)__cvta_generic_to_shared(sm);
    int vp = tid >> 3, vq = (tid & 7) * 4;

    #pragma unroll
    for (int t = 0; t < 2; t++) {
        int i = tid + t * 256;
        int r = i >> 3, f = (i & 7) * 4;
        cp16(sbase + (r * KW + f) * 4, Kb + (size_t)r * DD + f);
    }
    cp16(sbase + (KWORDS + vp * KW + vq) * 4,
         g_Vh + (size_t)(b * 256 + vp) * 256 + h * HDIM + vq);
    CP_COMMIT();

    for (int ci = 0; ci < 8; ci++) {
        CP_WAIT0();
        __syncthreads();

        if (ci + 1 < 8) {
            int c1  = (ci + 1) * 64;
            uint32_t dst = sbase + ((ci + 1) & 1) * BUFW * 4;
            #pragma unroll
            for (int t = 0; t < 2; t++) {
                int i = tid + t * 256;
                int r = i >> 3, f = (i & 7) * 4;
                cp16(dst + (r * KW + f) * 4, Kb + (size_t)(c1 + r) * DD + f);
            }
            cp16(dst + (KWORDS + vp * KW + vq) * 4,
                 g_Vh + (size_t)(b * 256 + (ci + 1) * 32 + vp) * 256 + h * HDIM + vq);
            CP_COMMIT();
        }

        const uint32_t* Ks = sm + (ci & 1) * BUFW;
        const uint32_t* Vs = Ks + KWORDS;
        int c0 = ci * 64;

        float sacc[8][4];
        #pragma unroll
        for (int nt = 0; nt < 8; nt++)
            #pragma unroll
            for (int r = 0; r < 4; r++) sacc[nt][r] = 0.f;
        #pragma unroll
        for (int nt = 0; nt < 8; nt++)
            #pragma unroll
            for (int kf = 0; kf < 4; kf++) {
                uint32_t b0v = Ks[(nt * 8 + grp) * KW + kf * 8 + tig];
                uint32_t b1v = Ks[(nt * 8 + grp) * KW + kf * 8 + tig + 4];
                mma_tf32(sacc[nt], qa[kf], b0v, b1v);
            }

        uint32_t wa0 = bm0[c0 >> 5], wa1 = bm0[(c0 >> 5) + 1];
        uint32_t wb0 = bm1[c0 >> 5], wb1 = bm1[(c0 >> 5) + 1];
        float cm0 = -3.4e38f, cm1 = -3.4e38f;
        #pragma unroll
        for (int nt = 0; nt < 8; nt++) {
            int j  = nt * 8 + 2 * tig;
            uint32_t wa = (j < 32) ? wa0 : wa1;
            uint32_t wb = (j < 32) ? wb0 : wb1;
            int sh = j & 31;
            if (!((wa >> sh) & 1))        sacc[nt][0] = -1e10f;
            if (!((wa >> (sh + 1)) & 1))  sacc[nt][1] = -1e10f;
            if (!((wb >> sh) & 1))        sacc[nt][2] = -1e10f;
            if (!((wb >> (sh + 1)) & 1))  sacc[nt][3] = -1e10f;
            cm0 = fmaxf(cm0, fmaxf(sacc[nt][0], sacc[nt][1]));
            cm1 = fmaxf(cm1, fmaxf(sacc[nt][2], sacc[nt][3]));
        }
        cm0 = fmaxf(cm0, __shfl_xor_sync(0xffffffffu, cm0, 1));
        cm0 = fmaxf(cm0, __shfl_xor_sync(0xffffffffu, cm0, 2));
        cm1 = fmaxf(cm1, __shfl_xor_sync(0xffffffffu, cm1, 1));
        cm1 = fmaxf(cm1, __shfl_xor_sync(0xffffffffu, cm1, 2));

        float nm0 = fmaxf(m0, cm0), nm1 = fmaxf(m1, cm1);
        float f0 = __expf((m0 - nm0) * escale), f1 = __expf((m1 - nm1) * escale);
        l0 *= f0; l1 *= f1;
        #pragma unroll
        for (int nt = 0; nt < 4; nt++) {
            oacc[nt][0] *= f0; oacc[nt][1] *= f0;
            oacc[nt][2] *= f1; oacc[nt][3] *= f1;
        }
        m0 = nm0; m1 = nm1;

        uint32_t h2a[8], h2b[8];
        #pragma unroll
        for (int nt = 0; nt < 8; nt++) {
            float p0 = __expf((sacc[nt][0] - nm0) * escale);
            float p1 = __expf((sacc[nt][1] - nm0) * escale);
            float p2 = __expf((sacc[nt][2] - nm1) * escale);
            float p3 = __expf((sacc[nt][3] - nm1) * escale);
            l0 += p0 + p1; l1 += p2 + p3;
            h2a[nt] = h2bits(p0, p1);
            h2b[nt] = h2bits(p2, p3);
        }

        #pragma unroll
        for (int s = 0; s < 4; s++) {
            uint32_t pa[4];
            pa[0] = h2a[2 * s];
            pa[1] = h2b[2 * s];
            pa[2] = h2a[2 * s + 1];
            pa[3] = h2b[2 * s + 1];
            #pragma unroll
            for (int nt = 0; nt < 4; nt++) {
                uint32_t b0v = Vs[(s * 8 + tig) * KW + nt * 8 + grp];
                uint32_t b1v = Vs[(s * 8 + tig + 4) * KW + nt * 8 + grp];
                mma_f16(oacc[nt], pa, b0v, b1v);
            }
        }
    }

    l0 += __shfl_xor_sync(0xffffffffu, l0, 1);
    l0 += __shfl_xor_sync(0xffffffffu, l0, 2);
    l1 += __shfl_xor_sync(0xffffffffu, l1, 1);
    l1 += __shfl_xor_sync(0xffffffffu, l1, 2);
    float inv0 = 1.f / l0, inv1 = 1.f / l1;

    uint32_t* o0 = g_atth + (size_t)(b * NN + qw + grp) * 128 + h * 16;
    uint32_t* o1 = g_atth + (size_t)(b * NN + qw + grp + 8) * 128 + h * 16;
    #pragma unroll
    for (int nt = 0; nt < 4; nt++) {
        o0[nt * 4 + tig] = h2bits(oacc[nt][0] * inv0, oacc[nt][1] * inv0);
        o1[nt * 4 + tig] = h2bits(oacc[nt][2] * inv1, oacc[nt][3] * inv1);
    }
}

// ---------------- launch ------------------------------------------------------
extern "C" void kernel_launch(void* const* d_in, const int* in_sizes, int n_in,
                              void* d_out, int out_size) {
    const float* query = (const float*)d_in[0];
    const float* key   = (const float*)d_in[1];
    const float* value = (const float*)d_in[2];
    const int*   edge  = (const int*)d_in[3];
    const int*   mask  = (const int*)d_in[4];
    const float* Wq = (const float*)d_in[5];
    const float* bq = (const float*)d_in[6];
    const float* Wk = (const float*)d_in[7];
    const float* bk = (const float*)d_in[8];
    const float* Wv = (const float*)d_in[9];
    const float* bv = (const float*)d_in[10];
    const float* Wo = (const float*)d_in[11];
    const float* bo = (const float*)d_in[12];
    float* out = (float*)d_out;

    float *Qp, *Kp;
    uint32_t *Xh, *Wp, *atth;
    cudaGetSymbolAddress((void**)&Qp,  g_Q);
    cudaGetSymbolAddress((void**)&Kp,  g_K);
    cudaGetSymbolAddress((void**)&Xh,  g_Xh);
    cudaGetSymbolAddress((void**)&Wp,  g_Wp);
    cudaGetSymbolAddress((void**)&atth, g_atth);

    cudaFuncSetAttribute(k_attn, cudaFuncAttributeMaxDynamicSharedMemorySize,
                         ATT_SMEM);

    // 1: inputs->fp16, W->fp16 pairs, zero A, pack mask
    k_round<<<2048, 256>>>(query, key, value, Wq, Wk, Wv, Wo, mask);

    // 2: graph prep + dense adjacency fill (single CTA)
    k_graph<<<1, NN>>>(edge);

    // 3: QKV projection (fp16 MMA; epilogue packs xwP; z=3 service: A->fp16)
    k_hgemm<<<dim3(2, 128, 4), 256>>>(Xh, Wp, nullptr, nullptr, 1);

    // 4: aggregation GEMM (fp16; z0/1 -> tf32 Q/K, z2 -> Vh)  (<- ncu slot)
    k_agg_h<<<dim3(2, 4, 96), 256>>>(bq, bk, bv, Qp, Kp);

    // 5: flash attention (tf32 QK + fp16 PV) -> fp16 att
    k_attn<<<dim3(4, HH, BB), 256, ATT_SMEM>>>(Qp, Kp);

    // 6: output projection (fp16 MMA; +bias, fp32) into d_out
    k_hgemm<<<dim3(2, 128, 1), 256>>>(atth, Wp + 3 * 128 * 256,
                                      out, bo, 0);
}

// round 17
// speedup vs baseline: 1.3439x; 1.0502x over previous
#include <cuda_runtime.h>
#include <cuda_fp16.h>
#include <cstdint>

#define BB   32
#define NN   512
#define DD   256
#define HH   8
#define HDIM 32
#define EE   16384
#define ETOT (EE + NN)

// ---------------- scratch (static device globals; no allocation) -------------
__device__ int      g_rowptr[NN + 1];
__device__ int2     g_edge[ETOT];
__device__ uint32_t g_bmask[NN * 16];
__device__ float    g_A[NN * NN];                 // fp32 adjacency (built once)
__device__ uint32_t g_Ah[NN * 256];               // fp16 adjacency, row-major pairs
__device__ uint32_t g_Xh[3 * BB * NN * 128];      // fp16 q/k/v inputs row-major
__device__ uint32_t g_Wp[4 * 128 * 256];          // fp16 W k-pair-packed [pair][n]
__device__ uint32_t g_xwP[3 * BB * 256 * 256];    // fp16 xw k-pair-packed
__device__ uint32_t g_Qh[BB * NN * 128];          // fp16 Q row-major d-pairs
__device__ uint32_t g_Kh[BB * NN * 128];          // fp16 K row-major d-pairs
__device__ uint32_t g_Vh[BB * 256 * 256];         // fp16 V kv-pairs
__device__ uint32_t g_atth[BB * NN * 128];        // fp16 attention output

// ---------------- helpers -----------------------------------------------------
__device__ __forceinline__ void mma_f16(float* c, const uint32_t* a,
                                        uint32_t b0, uint32_t b1) {
    asm volatile(
        "mma.sync.aligned.m16n8k16.row.col.f32.f16.f16.f32 "
        "{%0,%1,%2,%3}, {%4,%5,%6,%7}, {%8,%9}, {%0,%1,%2,%3};"
        : "+f"(c[0]), "+f"(c[1]), "+f"(c[2]), "+f"(c[3])
        : "r"(a[0]), "r"(a[1]), "r"(a[2]), "r"(a[3]), "r"(b0), "r"(b1));
}
__device__ __forceinline__ uint32_t h2bits(float a, float b) {
    __half2 h = __floats2half2_rn(a, b);
    return *reinterpret_cast<uint32_t*>(&h);
}
__device__ __forceinline__ void cp16(uint32_t saddr, const void* g) {
    asm volatile("cp.async.ca.shared.global [%0], [%1], 16;"
                 :: "r"(saddr), "l"(g) : "memory");
}
#define CP_COMMIT() asm volatile("cp.async.commit_group;" ::: "memory")
#define CP_WAIT0()  asm volatile("cp.async.wait_group 0;" ::: "memory")

// ---------------- prep: inputs->fp16, W->fp16 pairs, zero A, pack mask --------
__global__ void k_round(const float* __restrict__ q, const float* __restrict__ k,
                        const float* __restrict__ v,
                        const float* __restrict__ wq, const float* __restrict__ wk,
                        const float* __restrict__ wv, const float* __restrict__ wo,
                        const int* __restrict__ mask) {
    int idx = blockIdx.x * 256 + threadIdx.x;
    #pragma unroll
    for (int t = 0; t < 6; t++) {
        int i = idx + t * 524288;
        int j   = i >> 20;
        int off = i & 0xFFFFF;
        const float4* s = (j == 0) ? (const float4*)q
                        : (j == 1) ? (const float4*)k : (const float4*)v;
        float4 x = s[off];
        uint2 o;
        o.x = h2bits(x.x, x.y);
        o.y = h2bits(x.z, x.w);
        *(uint2*)(g_Xh + (size_t)j * 2097152 + (size_t)off * 2) = o;
    }
    if (idx < 65536) {
        int j   = idx >> 14;
        int rem = idx & 16383;
        int p   = rem >> 7;
        int n2  = (rem & 127) * 2;
        const float* w = (j == 0) ? wq : (j == 1) ? wk : (j == 2) ? wv : wo;
        float2 e = *(const float2*)(w + (size_t)(2 * p) * 256 + n2);
        float2 o = *(const float2*)(w + (size_t)(2 * p + 1) * 256 + n2);
        uint2 u;
        u.x = h2bits(e.x, o.x);
        u.y = h2bits(e.y, o.y);
        *(uint2*)(g_Wp + (size_t)(j * 128 + p) * 256 + n2) = u;
        ((float4*)g_A)[idx] = make_float4(0.f, 0.f, 0.f, 0.f);
    }
    if (idx < NN * 16) {
        int r  = idx >> 4;
        int wd = idx & 15;
        const int* mrow = mask + (size_t)r * NN + wd * 32;
        uint32_t bits = 0;
        #pragma unroll
        for (int jb = 0; jb < 32; jb++) bits |= (mrow[jb] ? 1u : 0u) << jb;
        g_bmask[idx] = bits;
    }
}

// ---------------- fused single-CTA graph prep + dense A fill ------------------
__global__ __launch_bounds__(NN) void k_graph(const int* __restrict__ edge) {
    __shared__ int sdeg[NN];
    __shared__ int scnt[NN];
    __shared__ int srow[NN];
    __shared__ int ss[NN];
    __shared__ int se64;
    int t = threadIdx.x;

    if (t == 0) {
        int nz = 0;
        for (int i = 0; i < 64; i++) nz += (edge[2 * i + 1] != 0);
        se64 = (nz == 0) ? 1 : 0;
    }
    sdeg[t] = 0;
    scnt[t] = 0;
    __syncthreads();
    int e64 = se64;

    for (int e = t; e < ETOT; e += NN) {
        int dst = (e < EE) ? (e64 ? edge[2 * (EE + e)] : edge[EE + e]) : (e - EE);
        if (dst >= 0 && dst < NN) atomicAdd(&sdeg[dst], 1);
    }
    __syncthreads();

    ss[t] = sdeg[t];
    __syncthreads();
    for (int off = 1; off < NN; off <<= 1) {
        int v = (t >= off) ? ss[t - off] : 0;
        __syncthreads();
        ss[t] += v;
        __syncthreads();
    }
    srow[t] = ss[t] - sdeg[t];
    g_rowptr[t + 1] = ss[t];
    if (t == 0) g_rowptr[0] = 0;
    __syncthreads();

    for (int e = t; e < ETOT; e += NN) {
        int s, d;
        if (e < EE) {
            s = e64 ? edge[2 * e] : edge[e];
            d = e64 ? edge[2 * (EE + e)] : edge[EE + e];
        } else {
            s = e - EE; d = e - EE;
        }
        if (s < 0 || s >= NN || d < 0 || d >= NN) continue;
        float nm = rsqrtf((float)sdeg[s]) * rsqrtf((float)sdeg[d]);
        int pos = srow[d] + atomicAdd(&scnt[d], 1);
        g_edge[pos] = make_int2(s, __float_as_int(nm));
    }
    __syncthreads();

    float* arow = g_A + (size_t)t * NN;
    for (int i = srow[t]; i < ss[t]; i++) {
        int2 e = g_edge[i];
        arow[e.x] += __int_as_float(e.y);
    }
}

// ---------------- fp16 cp.async GEMM (projection / output) --------------------
#define HA_ST 20
#define HB_ST 136
#define HA_BUF (128 * HA_ST)
#define HB_BUF (16 * HB_ST)

__global__ __launch_bounds__(256) void k_hgemm(
    const uint32_t* __restrict__ Abase,
    const uint32_t* __restrict__ Bbase,
    float* __restrict__ Cout,
    const float* __restrict__ bias, int packC)
{
    const int z = blockIdx.z;
    int tid = threadIdx.x;

    if (z == 3) {
        int cta = blockIdx.x * 128 + blockIdx.y;
        int i4  = cta * 256 + tid;
        float4 v = ((const float4*)g_A)[i4];
        uint2 o;
        o.x = h2bits(v.x, v.y);
        o.y = h2bits(v.z, v.w);
        *(uint2*)(g_Ah + (size_t)i4 * 2) = o;
        return;
    }

    __shared__ uint32_t Asb[2 * HA_BUF];
    __shared__ uint32_t Bsb[2 * HB_BUF];
    __shared__ float    bsh[128];

    const uint32_t* A  = Abase + (size_t)z * (BB * NN * 128);
    const uint32_t* Bp = Bbase + (size_t)z * (128 * 256);

    const int n0 = blockIdx.x * 128;
    const int m0 = blockIdx.y * 128;

    int wid  = tid >> 5;
    int lane = tid & 31;
    int grp  = lane >> 2;
    int tig  = lane & 3;
    int wm   = (wid & 1) * 64;
    int wn   = (wid >> 1) * 32;

    if (tid < 128) bsh[tid] = bias ? bias[n0 + tid] : 0.f;

    uint32_t sA = (uint32_t)__cvta_generic_to_shared(Asb);
    uint32_t sB = (uint32_t)__cvta_generic_to_shared(Bsb);

    float acc[4][4][4];
    #pragma unroll
    for (int i = 0; i < 4; i++)
        #pragma unroll
        for (int j = 0; j < 4; j++)
            #pragma unroll
            for (int r = 0; r < 4; r++) acc[i][j][r] = 0.f;

    #pragma unroll
    for (int t = 0; t < 2; t++) {
        int i = tid + t * 256;
        int row = i >> 2, q = (i & 3) * 4;
        cp16(sA + (row * HA_ST + q) * 4, A + (size_t)(m0 + row) * 128 + q);
    }
    #pragma unroll
    for (int t = 0; t < 2; t++) {
        int i = tid + t * 256;
        int pr = i >> 5, w = (i & 31) * 4;
        cp16(sB + (pr * HB_ST + w) * 4, Bp + (size_t)pr * 256 + n0 + w);
    }
    CP_COMMIT();

    for (int c = 0; c < 8; c++) {
        CP_WAIT0();
        __syncthreads();

        if (c + 1 < 8) {
            int buf = (c + 1) & 1;
            uint32_t dA = sA + buf * HA_BUF * 4;
            uint32_t dB = sB + buf * HB_BUF * 4;
            int kw = (c + 1) * 16;
            int pb = (c + 1) * 16;
            #pragma unroll
            for (int t = 0; t < 2; t++) {
                int i = tid + t * 256;
                int row = i >> 2, q = (i & 3) * 4;
                cp16(dA + (row * HA_ST + q) * 4,
                     A + (size_t)(m0 + row) * 128 + kw + q);
            }
            #pragma unroll
            for (int t = 0; t < 2; t++) {
                int i = tid + t * 256;
                int pr = i >> 5, w = (i & 31) * 4;
                cp16(dB + (pr * HB_ST + w) * 4,
                     Bp + (size_t)(pb + pr) * 256 + n0 + w);
            }
            CP_COMMIT();
        }

        const uint32_t* As = Asb + (c & 1) * HA_BUF;
        const uint32_t* Bs = Bsb + (c & 1) * HB_BUF;

        #pragma unroll
        for (int s = 0; s < 2; s++) {
            uint32_t af[4][4], bf[4][2];
            #pragma unroll
            for (int mt = 0; mt < 4; mt++) {
                int r = wm + mt * 16 + grp;
                af[mt][0] = As[r * HA_ST + 8 * s + tig];
                af[mt][1] = As[(r + 8) * HA_ST + 8 * s + tig];
                af[mt][2] = As[r * HA_ST + 8 * s + tig + 4];
                af[mt][3] = As[(r + 8) * HA_ST + 8 * s + tig + 4];
            }
            #pragma unroll
            for (int nt = 0; nt < 4; nt++) {
                int cc = wn + nt * 8 + grp;
                bf[nt][0] = Bs[(8 * s + tig) * HB_ST + cc];
                bf[nt][1] = Bs[(8 * s + tig + 4) * HB_ST + cc];
            }
            #pragma unroll
            for (int mt = 0; mt < 4; mt++)
                #pragma unroll
                for (int nt = 0; nt < 4; nt++)
                    mma_f16(acc[mt][nt], af[mt], bf[nt][0], bf[nt][1]);
        }
        __syncthreads();
    }

    if (packC) {
        int b = m0 >> 9;
        uint32_t* dst = g_xwP + (size_t)blockIdx.z * 2097152 + (size_t)b * 65536;
        #pragma unroll
        for (int mt = 0; mt < 4; mt++) {
            #pragma unroll
            for (int nt = 0; nt < 4; nt++) {
                int cc = n0 + wn + nt * 8 + tig * 2;
                float a0 = acc[mt][nt][0], a1 = acc[mt][nt][1];
                float a2 = acc[mt][nt][2], a3 = acc[mt][nt][3];
                float p0 = __shfl_xor_sync(0xffffffffu, a0, 4);
                float p1 = __shfl_xor_sync(0xffffffffu, a1, 4);
                float p2 = __shfl_xor_sync(0xffffffffu, a2, 4);
                float p3 = __shfl_xor_sync(0xffffffffu, a3, 4);
                if (!(grp & 1)) {
                    int r0 = (m0 & 511) + wm + mt * 16 + grp;
                    uint2 w0 = {h2bits(a0, p0), h2bits(a1, p1)};
                    uint2 w1 = {h2bits(a2, p2), h2bits(a3, p3)};
                    *(uint2*)(dst + (size_t)(r0 >> 1) * 256 + cc) = w0;
                    *(uint2*)(dst + (size_t)((r0 + 8) >> 1) * 256 + cc) = w1;
                }
            }
        }
    } else {
        #pragma unroll
        for (int mt = 0; mt < 4; mt++) {
            #pragma unroll
            for (int nt = 0; nt < 4; nt++) {
                int cc = wn + nt * 8 + tig * 2;
                float b0 = bsh[cc], b1 = bsh[cc + 1];
                size_t r0 = (size_t)(m0 + wm + mt * 16 + grp) * 256 + n0 + cc;
                size_t r1 = r0 + 8 * 256;
                float2 v0 = {acc[mt][nt][0] + b0, acc[mt][nt][1] + b1};
                float2 v1 = {acc[mt][nt][2] + b0, acc[mt][nt][3] + b1};
                *(float2*)(Cout + r0) = v0;
                *(float2*)(Cout + r1) = v1;
            }
        }
    }
}

// ---------------- fp16 aggregation GEMM ---------------------------------------
// z=0/1: fp16 Q/K row-major d-pairs.  z=2: fp16 kv-pair-packed g_Vh.
__global__ __launch_bounds__(256) void k_agg_h(
    const float* __restrict__ bq, const float* __restrict__ bk,
    const float* __restrict__ bv)
{
    __shared__ uint32_t Asb[2 * HA_BUF];
    __shared__ uint32_t Bsb[2 * HB_BUF];
    __shared__ float    bsh[128];

    int zz = blockIdx.z;
    int z  = zz >> 5;
    int b  = zz & 31;
    const float* bias = (z == 0) ? bq : (z == 1) ? bk : bv;
    const uint32_t* Bp = g_xwP + (size_t)z * 2097152 + (size_t)b * 65536;

    const int n0 = blockIdx.x * 128;
    const int m0 = blockIdx.y * 128;

    int tid  = threadIdx.x;
    int wid  = tid >> 5;
    int lane = tid & 31;
    int grp  = lane >> 2;
    int tig  = lane & 3;
    int wm   = (wid & 1) * 64;
    int wn   = (wid >> 1) * 32;

    if (tid < 128) bsh[tid] = bias[n0 + tid];

    uint32_t sA = (uint32_t)__cvta_generic_to_shared(Asb);
    uint32_t sB = (uint32_t)__cvta_generic_to_shared(Bsb);

    float acc[4][4][4];
    #pragma unroll
    for (int i = 0; i < 4; i++)
        #pragma unroll
        for (int j = 0; j < 4; j++)
            #pragma unroll
            for (int r = 0; r < 4; r++) acc[i][j][r] = 0.f;

    #pragma unroll
    for (int t = 0; t < 2; t++) {
        int i = tid + t * 256;
        int row = i >> 2, q = (i & 3) * 4;
        cp16(sA + (row * HA_ST + q) * 4, g_Ah + (size_t)(m0 + row) * 256 + q);
    }
    #pragma unroll
    for (int t = 0; t < 2; t++) {
        int i = tid + t * 256;
        int pr = i >> 5, w = (i & 31) * 4;
        cp16(sB + (pr * HB_ST + w) * 4, Bp + (size_t)pr * 256 + n0 + w);
    }
    CP_COMMIT();

    for (int c = 0; c < 16; c++) {
        CP_WAIT0();
        __syncthreads();

        if (c + 1 < 16) {
            int buf = (c + 1) & 1;
            uint32_t dA = sA + buf * HA_BUF * 4;
            uint32_t dB = sB + buf * HB_BUF * 4;
            int kw = (c + 1) * 16;
            int pb = (c + 1) * 16;
            #pragma unroll
            for (int t = 0; t < 2; t++) {
                int i = tid + t * 256;
                int row = i >> 2, q = (i & 3) * 4;
                cp16(dA + (row * HA_ST + q) * 4,
                     g_Ah + (size_t)(m0 + row) * 256 + kw + q);
            }
            #pragma unroll
            for (int t = 0; t < 2; t++) {
                int i = tid + t * 256;
                int pr = i >> 5, w = (i & 31) * 4;
                cp16(dB + (pr * HB_ST + w) * 4,
                     Bp + (size_t)(pb + pr) * 256 + n0 + w);
            }
            CP_COMMIT();
        }

        const uint32_t* As = Asb + (c & 1) * HA_BUF;
        const uint32_t* Bs = Bsb + (c & 1) * HB_BUF;

        #pragma unroll
        for (int s = 0; s < 2; s++) {
            uint32_t af[4][4], bf[4][2];
            #pragma unroll
            for (int mt = 0; mt < 4; mt++) {
                int r = wm + mt * 16 + grp;
                af[mt][0] = As[r * HA_ST + 8 * s + tig];
                af[mt][1] = As[(r + 8) * HA_ST + 8 * s + tig];
                af[mt][2] = As[r * HA_ST + 8 * s + tig + 4];
                af[mt][3] = As[(r + 8) * HA_ST + 8 * s + tig + 4];
            }
            #pragma unroll
            for (int nt = 0; nt < 4; nt++) {
                int cc = wn + nt * 8 + grp;
                bf[nt][0] = Bs[(8 * s + tig) * HB_ST + cc];
                bf[nt][1] = Bs[(8 * s + tig + 4) * HB_ST + cc];
            }
            #pragma unroll
            for (int mt = 0; mt < 4; mt++)
                #pragma unroll
                for (int nt = 0; nt < 4; nt++)
                    mma_f16(acc[mt][nt], af[mt], bf[nt][0], bf[nt][1]);
        }
        __syncthreads();
    }

    if (z == 2) {
        // V: pair adjacent kv rows -> g_Vh
        uint32_t* dst = g_Vh + (size_t)b * 65536;
        #pragma unroll
        for (int mt = 0; mt < 4; mt++) {
            #pragma unroll
            for (int nt = 0; nt < 4; nt++) {
                int ccl = wn + nt * 8 + tig * 2;
                int cc  = n0 + ccl;
                float b0 = bsh[ccl], b1 = bsh[ccl + 1];
                float a0 = acc[mt][nt][0] + b0, a1 = acc[mt][nt][1] + b1;
                float a2 = acc[mt][nt][2] + b0, a3 = acc[mt][nt][3] + b1;
                float p0 = __shfl_xor_sync(0xffffffffu, a0, 4);
                float p1 = __shfl_xor_sync(0xffffffffu, a1, 4);
                float p2 = __shfl_xor_sync(0xffffffffu, a2, 4);
                float p3 = __shfl_xor_sync(0xffffffffu, a3, 4);
                if (!(grp & 1)) {
                    int r0 = m0 + wm + mt * 16 + grp;
                    uint2 w0 = {h2bits(a0, p0), h2bits(a1, p1)};
                    uint2 w1 = {h2bits(a2, p2), h2bits(a3, p3)};
                    *(uint2*)(dst + (size_t)(r0 >> 1) * 256 + cc) = w0;
                    *(uint2*)(dst + (size_t)((r0 + 8) >> 1) * 256 + cc) = w1;
                }
            }
        }
    } else {
        // Q/K: fp16 row-major d-pairs (cols 2tig,2tig+1 adjacent -> lane-local)
        uint32_t* dst = ((z == 0) ? g_Qh : g_Kh) + (size_t)b * (NN * 128);
        #pragma unroll
        for (int mt = 0; mt < 4; mt++) {
            #pragma unroll
            for (int nt = 0; nt < 4; nt++) {
                int ccl = wn + nt * 8 + tig * 2;
                float b0 = bsh[ccl], b1 = bsh[ccl + 1];
                int wd = (n0 + ccl) >> 1;
                int r0 = m0 + wm + mt * 16 + grp;
                dst[(size_t)r0 * 128 + wd] =
                    h2bits(acc[mt][nt][0] + b0, acc[mt][nt][1] + b1);
                dst[(size_t)(r0 + 8) * 128 + wd] =
                    h2bits(acc[mt][nt][2] + b0, acc[mt][nt][3] + b1);
            }
        }
    }
}

// ---------------- flash attention: full fp16 MMA ------------------------------
#define KST 20
#define KWORDS (64 * KST)
#define VST 36
#define VWORDS (32 * VST)
#define BUFW (KWORDS + VWORDS)
#define ATT_SMEM (2 * BUFW * 4)

__global__ __launch_bounds__(256, 2) void k_attn() {
    extern __shared__ uint32_t sm[];

    int h   = blockIdx.y;
    int b   = blockIdx.z;
    int tid = threadIdx.x;
    int wid = tid >> 5, lane = tid & 31;
    int grp = lane >> 2, tig = lane & 3;
    int qw  = blockIdx.x * 128 + wid * 16;

    const uint32_t* Qb = g_Qh + (size_t)b * (NN * 128) + h * 16;
    const uint32_t* Kb = g_Kh + (size_t)b * (NN * 128) + h * 16;

    const float escale = 0.17677669529663687f;

    // Q a-frags (fp16 k16): 2 k-steps x 4 words, lane-local
    uint32_t qa[2][4];
    #pragma unroll
    for (int s = 0; s < 2; s++) {
        qa[s][0] = Qb[(size_t)(qw + grp) * 128 + 8 * s + tig];
        qa[s][1] = Qb[(size_t)(qw + grp + 8) * 128 + 8 * s + tig];
        qa[s][2] = Qb[(size_t)(qw + grp) * 128 + 8 * s + tig + 4];
        qa[s][3] = Qb[(size_t)(qw + grp + 8) * 128 + 8 * s + tig + 4];
    }

    float m0 = -3.4e38f, m1 = -3.4e38f, l0 = 0.f, l1 = 0.f;
    float oacc[4][4];
    #pragma unroll
    for (int nt = 0; nt < 4; nt++)
        #pragma unroll
        for (int r = 0; r < 4; r++) oacc[nt][r] = 0.f;

    const uint32_t* bm0 = g_bmask + (size_t)(qw + grp) * 16;
    const uint32_t* bm1 = g_bmask + (size_t)(qw + grp + 8) * 16;

    uint32_t sbase = (uint32_t)__cvta_generic_to_shared(sm);
    int kr = tid >> 2, kq = (tid & 3) * 4;
    int vp = tid >> 3, vq = (tid & 7) * 4;

    // prologue chunk 0: K 64x16 words, V 32x32 words
    cp16(sbase + (kr * KST + kq) * 4, Kb + (size_t)kr * 128 + kq);
    cp16(sbase + (KWORDS + vp * VST + vq) * 4,
         g_Vh + (size_t)(b * 256 + vp) * 256 + h * HDIM + vq);
    CP_COMMIT();

    for (int ci = 0; ci < 8; ci++) {
        CP_WAIT0();
        __syncthreads();

        if (ci + 1 < 8) {
            int c1  = (ci + 1) * 64;
            uint32_t dst = sbase + ((ci + 1) & 1) * BUFW * 4;
            cp16(dst + (kr * KST + kq) * 4, Kb + (size_t)(c1 + kr) * 128 + kq);
            cp16(dst + (KWORDS + vp * VST + vq) * 4,
                 g_Vh + (size_t)(b * 256 + (ci + 1) * 32 + vp) * 256 + h * HDIM + vq);
            CP_COMMIT();
        }

        const uint32_t* Ks = sm + (ci & 1) * BUFW;
        const uint32_t* Vs = Ks + KWORDS;
        int c0 = ci * 64;

        // S = Q K^T (fp16 k16: 8 n-tiles x 2 k-steps)
        float sacc[8][4];
        #pragma unroll
        for (int nt = 0; nt < 8; nt++)
            #pragma unroll
            for (int r = 0; r < 4; r++) sacc[nt][r] = 0.f;
        #pragma unroll
        for (int nt = 0; nt < 8; nt++)
            #pragma unroll
            for (int s = 0; s < 2; s++) {
                uint32_t b0v = Ks[(nt * 8 + grp) * KST + 8 * s + tig];
                uint32_t b1v = Ks[(nt * 8 + grp) * KST + 8 * s + tig + 4];
                mma_f16(sacc[nt], qa[s], b0v, b1v);
            }

        uint32_t wa0 = bm0[c0 >> 5], wa1 = bm0[(c0 >> 5) + 1];
        uint32_t wb0 = bm1[c0 >> 5], wb1 = bm1[(c0 >> 5) + 1];
        float cm0 = -3.4e38f, cm1 = -3.4e38f;
        #pragma unroll
        for (int nt = 0; nt < 8; nt++) {
            int j  = nt * 8 + 2 * tig;
            uint32_t wa = (j < 32) ? wa0 : wa1;
            uint32_t wb = (j < 32) ? wb0 : wb1;
            int sh = j & 31;
            if (!((wa >> sh) & 1))        sacc[nt][0] = -1e10f;
            if (!((wa >> (sh + 1)) & 1))  sacc[nt][1] = -1e10f;
            if (!((wb >> sh) & 1))        sacc[nt][2] = -1e10f;
            if (!((wb >> (sh + 1)) & 1))  sacc[nt][3] = -1e10f;
            cm0 = fmaxf(cm0, fmaxf(sacc[nt][0], sacc[nt][1]));
            cm1 = fmaxf(cm1, fmaxf(sacc[nt][2], sacc[nt][3]));
        }
        cm0 = fmaxf(cm0, __shfl_xor_sync(0xffffffffu, cm0, 1));
        cm0 = fmaxf(cm0, __shfl_xor_sync(0xffffffffu, cm0, 2));
        cm1 = fmaxf(cm1, __shfl_xor_sync(0xffffffffu, cm1, 1));
        cm1 = fmaxf(cm1, __shfl_xor_sync(0xffffffffu, cm1, 2));

        float nm0 = fmaxf(m0, cm0), nm1 = fmaxf(m1, cm1);
        float f0 = __expf((m0 - nm0) * escale), f1 = __expf((m1 - nm1) * escale);
        l0 *= f0; l1 *= f1;
        #pragma unroll
        for (int nt = 0; nt < 4; nt++) {
            oacc[nt][0] *= f0; oacc[nt][1] *= f0;
            oacc[nt][2] *= f1; oacc[nt][3] *= f1;
        }
        m0 = nm0; m1 = nm1;

        uint32_t h2a[8], h2b[8];
        #pragma unroll
        for (int nt = 0; nt < 8; nt++) {
            float p0 = __expf((sacc[nt][0] - nm0) * escale);
            float p1 = __expf((sacc[nt][1] - nm0) * escale);
            float p2 = __expf((sacc[nt][2] - nm1) * escale);
            float p3 = __expf((sacc[nt][3] - nm1) * escale);
            l0 += p0 + p1; l1 += p2 + p3;
            h2a[nt] = h2bits(p0, p1);
            h2b[nt] = h2bits(p2, p3);
        }

        #pragma unroll
        for (int s = 0; s < 4; s++) {
            uint32_t pa[4];
            pa[0] = h2a[2 * s];
            pa[1] = h2b[2 * s];
            pa[2] = h2a[2 * s + 1];
            pa[3] = h2b[2 * s + 1];
            #pragma unroll
            for (int nt = 0; nt < 4; nt++) {
                uint32_t b0v = Vs[(s * 8 + tig) * VST + nt * 8 + grp];
                uint32_t b1v = Vs[(s * 8 + tig + 4) * VST + nt * 8 + grp];
                mma_f16(oacc[nt], pa, b0v, b1v);
            }
        }
    }

    l0 += __shfl_xor_sync(0xffffffffu, l0, 1);
    l0 += __shfl_xor_sync(0xffffffffu, l0, 2);
    l1 += __shfl_xor_sync(0xffffffffu, l1, 1);
    l1 += __shfl_xor_sync(0xffffffffu, l1, 2);
    float inv0 = 1.f / l0, inv1 = 1.f / l1;

    uint32_t* o0 = g_atth + (size_t)(b * NN + qw + grp) * 128 + h * 16;
    uint32_t* o1 = g_atth + (size_t)(b * NN + qw + grp + 8) * 128 + h * 16;
    #pragma unroll
    for (int nt = 0; nt < 4; nt++) {
        o0[nt * 4 + tig] = h2bits(oacc[nt][0] * inv0, oacc[nt][1] * inv0);
        o1[nt * 4 + tig] = h2bits(oacc[nt][2] * inv1, oacc[nt][3] * inv1);
    }
}

// ---------------- launch ------------------------------------------------------
extern "C" void kernel_launch(void* const* d_in, const int* in_sizes, int n_in,
                              void* d_out, int out_size) {
    const float* query = (const float*)d_in[0];
    const float* key   = (const float*)d_in[1];
    const float* value = (const float*)d_in[2];
    const int*   edge  = (const int*)d_in[3];
    const int*   mask  = (const int*)d_in[4];
    const float* Wq = (const float*)d_in[5];
    const float* bq = (const float*)d_in[6];
    const float* Wk = (const float*)d_in[7];
    const float* bk = (const float*)d_in[8];
    const float* Wv = (const float*)d_in[9];
    const float* bv = (const float*)d_in[10];
    const float* Wo = (const float*)d_in[11];
    const float* bo = (const float*)d_in[12];
    float* out = (float*)d_out;

    uint32_t *Xh, *Wp, *atth;
    cudaGetSymbolAddress((void**)&Xh,  g_Xh);
    cudaGetSymbolAddress((void**)&Wp,  g_Wp);
    cudaGetSymbolAddress((void**)&atth, g_atth);

    cudaFuncSetAttribute(k_attn, cudaFuncAttributeMaxDynamicSharedMemorySize,
                         ATT_SMEM);

    // 1: inputs->fp16, W->fp16 pairs, zero A, pack mask
    k_round<<<2048, 256>>>(query, key, value, Wq, Wk, Wv, Wo, mask);

    // 2: graph prep + dense adjacency fill (single CTA)
    k_graph<<<1, NN>>>(edge);

    // 3: QKV projection (fp16 MMA; epilogue packs xwP; z=3 service: A->fp16)
    k_hgemm<<<dim3(2, 128, 4), 256>>>(Xh, Wp, nullptr, nullptr, 1);

    // 4: aggregation GEMM (fp16; z0/1 -> fp16 Q/K, z2 -> Vh)  (<- ncu slot)
    k_agg_h<<<dim3(2, 4, 96), 256>>>(bq, bk, bv);

    // 5: flash attention (all-fp16 MMA) -> fp16 att
    k_attn<<<dim3(4, HH, BB), 256, ATT_SMEM>>>();

    // 6: output projection (fp16 MMA; +bias, fp32) into d_out
    k_hgemm<<<dim3(2, 128, 1), 256>>>(atth, Wp + 3 * 128 * 256,
                                      out, bo, 0);
}